// round 3
// baseline (speedup 1.0000x reference)
#include <cuda_runtime.h>

#define Nn 20000
#define Ee 320000
#define NSc 128
#define NHd 128
#define NVc 16
#define TBE 16   // edges per block
#define TN  8    // nodes per block

// ---------------- scratch (device globals; no allocation) ----------------
__device__ float g_maggr[Nn * NHd];      // segment-sum of m over rec
__device__ float g_paggr[Nn * NVc * 8];  // segment-sum of pos_m over rec
__device__ float g_deg[Nn];              // bincount(send)

// blade -> grade (repeats [1,3,3,1])
__constant__ int c_grade[8] = {0, 1, 1, 1, 2, 2, 2, 3};

// Cayley tables for Cl(3,0), blade order 1,e1,e2,e3,e12,e13,e23,e123.
// out[RES[i][j]] += SGN[i][j] * a[i] * b[j]
__device__ constexpr int RES[8][8] = {
    {0,1,2,3,4,5,6,7},
    {1,0,4,5,2,3,7,6},
    {2,4,0,6,1,7,3,5},
    {3,5,6,0,7,1,2,4},
    {4,2,1,7,0,6,5,3},
    {5,3,7,1,6,0,4,2},
    {6,7,3,2,5,4,0,1},
    {7,6,5,4,3,2,1,0}};
__device__ constexpr float SGN[8][8] = {
    { 1, 1, 1, 1, 1, 1, 1, 1},
    { 1, 1, 1, 1, 1, 1, 1, 1},
    { 1,-1, 1, 1,-1,-1, 1,-1},
    { 1,-1,-1, 1, 1,-1,-1, 1},
    { 1,-1, 1, 1,-1,-1, 1,-1},
    { 1,-1,-1, 1, 1,-1,-1, 1},
    { 1, 1,-1, 1,-1, 1,-1,-1},
    { 1, 1,-1, 1,-1, 1,-1,-1}};

// ---------------- kernel 0: zero the scratch ----------------
__global__ __launch_bounds__(256) void zero_kernel() {
    const int tot = Nn * NHd + Nn * NVc * 8 + Nn;
    for (int i = blockIdx.x * blockDim.x + threadIdx.x; i < tot;
         i += gridDim.x * blockDim.x) {
        if (i < Nn * NHd) g_maggr[i] = 0.f;
        else if (i < Nn * NHd + Nn * NVc * 8) g_paggr[i - Nn * NHd] = 0.f;
        else g_deg[i - Nn * NHd - Nn * NVc * 8] = 0.f;
    }
}

// ---------------- kernel 1: per-edge message path ----------------
__global__ __launch_bounds__(128) void edge_kernel(
    const float* __restrict__ s, const float* __restrict__ v,
    const int* __restrict__ ei,
    const float* __restrict__ Wv_w, const float* __restrict__ Wv_b,
    const float* __restrict__ W1, const float* __restrict__ b1,
    const float* __restrict__ W2, const float* __restrict__ b2,
    const float* __restrict__ P1, const float* __restrict__ pb1,
    const float* __restrict__ P2, const float* __restrict__ pb2)
{
    __shared__ __align__(16) float xs[TBE][272];    // [s_i | s_j | edge_attr]
    __shared__ __align__(16) float vij[TBE][128];   // MVLinear(v_j - v_i)
    __shared__ __align__(16) float bufA[TBE][128];  // d, then h1, then h2
    __shared__ __align__(16) float mbuf[TBE][128];  // m
    __shared__ float pm[TBE][16];
    __shared__ float wv[1024];
    __shared__ float wvb[16];
    __shared__ int snd[TBE], rcv[TBE];

    const int tid = threadIdx.x;
    const int e0 = blockIdx.x * TBE;

    if (tid < TBE) {
        snd[tid] = ei[e0 + tid];
        rcv[tid] = ei[Ee + e0 + tid];
    }
    for (int i = tid; i < 1024; i += 128) wv[i] = Wv_w[i];
    if (tid < 16) wvb[tid] = Wv_b[tid];
    __syncthreads();

    // d = v[rec] - v[send]  (into bufA) and scalar features into xs
    for (int idx = tid; idx < TBE * 128; idx += 128) {
        int e = idx >> 7, z = idx & 127;
        bufA[e][z] = v[rcv[e] * 128 + z] - v[snd[e] * 128 + z];
    }
    for (int idx = tid; idx < TBE * 128; idx += 128) {
        int e = idx >> 7, c = idx & 127;
        xs[e][c]       = s[snd[e] * 128 + c];
        xs[e][128 + c] = s[rcv[e] * 128 + c];
    }
    if (tid < TBE) atomicAdd(&g_deg[snd[tid]], 1.0f);
    __syncthreads();

    // v_ij = MVLinear(d): per-blade 16x16 matvec with grade-shared weights
    for (int idx = tid; idx < TBE * 128; idx += 128) {
        int e = idx >> 7, z = idx & 127;
        int o = z >> 3, bl = z & 7;
        int g = c_grade[bl];
        float acc = (bl == 0) ? wvb[o] : 0.f;
        #pragma unroll
        for (int c = 0; c < 16; c++)
            acc += bufA[e][c * 8 + bl] * wv[o * 64 + c * 4 + g];
        vij[e][z] = acc;
    }
    __syncthreads();

    // edge_attr = sum over blades of v_ij^2 -> xs[...,256+o]
    for (int idx = tid; idx < TBE * 16; idx += 128) {
        int e = idx >> 4, o = idx & 15;
        float acc = 0.f;
        #pragma unroll
        for (int bl = 0; bl < 8; bl++) { float x = vij[e][o * 8 + bl]; acc += x * x; }
        xs[e][256 + o] = acc;
    }
    __syncthreads();

    // message MLP layer1: 272 -> 128, relu  (bufA is free now)
    {
        float acc[TBE];
        float bb = b1[tid];
        #pragma unroll
        for (int e = 0; e < TBE; e++) acc[e] = bb;
        for (int k = 0; k < 272; k += 4) {
            float w0 = W1[(k + 0) * 128 + tid];
            float w1 = W1[(k + 1) * 128 + tid];
            float w2 = W1[(k + 2) * 128 + tid];
            float w3 = W1[(k + 3) * 128 + tid];
            #pragma unroll
            for (int e = 0; e < TBE; e++) {
                float4 x = *(const float4*)&xs[e][k];
                acc[e] += x.x * w0 + x.y * w1 + x.z * w2 + x.w * w3;
            }
        }
        #pragma unroll
        for (int e = 0; e < TBE; e++) bufA[e][tid] = fmaxf(acc[e], 0.f);
    }
    __syncthreads();

    // message MLP layer2: 128 -> 128 -> mbuf
    {
        float acc[TBE];
        float bb = b2[tid];
        #pragma unroll
        for (int e = 0; e < TBE; e++) acc[e] = bb;
        for (int k = 0; k < 128; k += 4) {
            float w0 = W2[(k + 0) * 128 + tid];
            float w1 = W2[(k + 1) * 128 + tid];
            float w2 = W2[(k + 2) * 128 + tid];
            float w3 = W2[(k + 3) * 128 + tid];
            #pragma unroll
            for (int e = 0; e < TBE; e++) {
                float4 x = *(const float4*)&bufA[e][k];
                acc[e] += x.x * w0 + x.y * w1 + x.z * w2 + x.w * w3;
            }
        }
        #pragma unroll
        for (int e = 0; e < TBE; e++) mbuf[e][tid] = acc[e];
    }
    __syncthreads();

    // pos MLP layer1: 128 -> 128, relu  (into bufA)
    {
        float acc[TBE];
        float bb = pb1[tid];
        #pragma unroll
        for (int e = 0; e < TBE; e++) acc[e] = bb;
        for (int k = 0; k < 128; k += 4) {
            float w0 = P1[(k + 0) * 128 + tid];
            float w1 = P1[(k + 1) * 128 + tid];
            float w2 = P1[(k + 2) * 128 + tid];
            float w3 = P1[(k + 3) * 128 + tid];
            #pragma unroll
            for (int e = 0; e < TBE; e++) {
                float4 x = *(const float4*)&mbuf[e][k];
                acc[e] += x.x * w0 + x.y * w1 + x.z * w2 + x.w * w3;
            }
        }
        #pragma unroll
        for (int e = 0; e < TBE; e++) bufA[e][tid] = fmaxf(acc[e], 0.f);
    }
    __syncthreads();

    // pos MLP layer2: 128 -> 16
    for (int idx = tid; idx < TBE * 16; idx += 128) {
        int e = idx >> 4, o = idx & 15;
        float acc = pb2[o];
        for (int k = 0; k < 128; k++) acc += bufA[e][k] * P2[k * 16 + o];
        pm[e][o] = acc;
    }
    __syncthreads();

    // scatter (segment-sum over rec) via REDG
    for (int idx = tid; idx < TBE * 128; idx += 128) {
        int e = idx >> 7, c = idx & 127;
        atomicAdd(&g_maggr[rcv[e] * 128 + c], mbuf[e][c]);
    }
    for (int idx = tid; idx < TBE * 128; idx += 128) {
        int e = idx >> 7, z = idx & 127;
        atomicAdd(&g_paggr[rcv[e] * 128 + z], vij[e][z] * pm[e][z >> 3]);
    }
}

// ---------------- kernel 2: per-node update ----------------
__global__ __launch_bounds__(128) void node_kernel(
    const float* __restrict__ s, const float* __restrict__ v,
    const float* __restrict__ U1, const float* __restrict__ ub1,
    const float* __restrict__ U2, const float* __restrict__ ub2,
    const float* __restrict__ gl_w, const float* __restrict__ gl_b,
    const float* __restrict__ gr_w, const float* __restrict__ gr_b,
    const float* __restrict__ go_w, const float* __restrict__ go_b,
    const float* __restrict__ ln_a,
    float* __restrict__ out_s, float* __restrict__ out_v)
{
    __shared__ __align__(16) float y[TN][256];   // [s | m_aggr*inv], later [vl | vr]
    __shared__ __align__(16) float h[TN][128];   // un hidden, later gp(vl,vr)
    __shared__ __align__(16) float p[TN][128];   // p_aggr * inv
    __shared__ __align__(16) float vo[TN][128];
    __shared__ float cn[TN][16];
    __shared__ float nrm[TN];
    __shared__ float dinv[TN];
    __shared__ float wl[1024], wr[1024], wo[2048];
    __shared__ float wlb[16], wrb[16], wob[16], lna[16];

    const int tid = threadIdx.x;
    const int n0 = blockIdx.x * TN;

    for (int i = tid; i < 1024; i += 128) { wl[i] = gl_w[i]; wr[i] = gr_w[i]; }
    for (int i = tid; i < 2048; i += 128) wo[i] = go_w[i];
    if (tid < 16) { wlb[tid] = gl_b[tid]; wrb[tid] = gr_b[tid];
                    wob[tid] = go_b[tid]; lna[tid] = ln_a[tid]; }
    if (tid < TN) dinv[tid] = rsqrtf(g_deg[n0 + tid]);
    __syncthreads();

    for (int idx = tid; idx < TN * 128; idx += 128) {
        int n = idx >> 7, c = idx & 127;
        y[n][c]       = s[(n0 + n) * 128 + c];
        y[n][128 + c] = g_maggr[(n0 + n) * 128 + c] * dinv[n];
        p[n][c]       = g_paggr[(n0 + n) * 128 + c] * dinv[n];
    }
    __syncthreads();

    // un layer1: 256 -> 128, relu
    {
        float acc[TN];
        float bb = ub1[tid];
        #pragma unroll
        for (int n = 0; n < TN; n++) acc[n] = bb;
        for (int k = 0; k < 256; k += 4) {
            float w0 = U1[(k + 0) * 128 + tid];
            float w1 = U1[(k + 1) * 128 + tid];
            float w2 = U1[(k + 2) * 128 + tid];
            float w3 = U1[(k + 3) * 128 + tid];
            #pragma unroll
            for (int n = 0; n < TN; n++) {
                float4 x = *(const float4*)&y[n][k];
                acc[n] += x.x * w0 + x.y * w1 + x.z * w2 + x.w * w3;
            }
        }
        #pragma unroll
        for (int n = 0; n < TN; n++) h[n][tid] = fmaxf(acc[n], 0.f);
    }
    __syncthreads();

    // un layer2 + residual -> out_s
    {
        float acc[TN];
        float bb = ub2[tid];
        #pragma unroll
        for (int n = 0; n < TN; n++) acc[n] = bb;
        for (int k = 0; k < 128; k += 4) {
            float w0 = U2[(k + 0) * 128 + tid];
            float w1 = U2[(k + 1) * 128 + tid];
            float w2 = U2[(k + 2) * 128 + tid];
            float w3 = U2[(k + 3) * 128 + tid];
            #pragma unroll
            for (int n = 0; n < TN; n++) {
                float4 x = *(const float4*)&h[n][k];
                acc[n] += x.x * w0 + x.y * w1 + x.z * w2 + x.w * w3;
            }
        }
        #pragma unroll
        for (int n = 0; n < TN; n++)
            out_s[(n0 + n) * 128 + tid] = y[n][tid] + acc[n];
    }
    __syncthreads();  // y now reusable

    // vl / vr = MVLinear(p_aggr) into y
    for (int idx = tid; idx < TN * 128; idx += 128) {
        int n = idx >> 7, z = idx & 127, o = z >> 3, bl = z & 7;
        int g = c_grade[bl];
        float al = (bl == 0) ? wlb[o] : 0.f;
        float ar = (bl == 0) ? wrb[o] : 0.f;
        #pragma unroll
        for (int c = 0; c < 16; c++) {
            float pv = p[n][c * 8 + bl];
            al += pv * wl[o * 64 + c * 4 + g];
            ar += pv * wr[o * 64 + c * 4 + g];
        }
        y[n][z] = al;
        y[n][128 + z] = ar;
    }
    __syncthreads();

    // channelwise geometric product gp(vl, vr) -> h
    for (int idx = tid; idx < TN * 16; idx += 128) {
        int n = idx >> 4, c = idx & 15;
        float a[8], b[8], o8[8];
        #pragma unroll
        for (int i = 0; i < 8; i++) {
            a[i] = y[n][c * 8 + i];
            b[i] = y[n][128 + c * 8 + i];
            o8[i] = 0.f;
        }
        #pragma unroll
        for (int i = 0; i < 8; i++)
            #pragma unroll
            for (int j = 0; j < 8; j++)
                o8[RES[i][j]] += SGN[i][j] * a[i] * b[j];
        #pragma unroll
        for (int k = 0; k < 8; k++) h[n][c * 8 + k] = o8[k];
    }
    __syncthreads();

    // vo = MVLinear(cat(gp, p_aggr)) with go_w (16 out, 32 in, 4)
    for (int idx = tid; idx < TN * 128; idx += 128) {
        int n = idx >> 7, z = idx & 127, o = z >> 3, bl = z & 7;
        int g = c_grade[bl];
        float acc = (bl == 0) ? wob[o] : 0.f;
        #pragma unroll
        for (int c = 0; c < 16; c++)
            acc += h[n][c * 8 + bl] * wo[o * 128 + c * 4 + g];
        #pragma unroll
        for (int c = 0; c < 16; c++)
            acc += p[n][c * 8 + bl] * wo[o * 128 + (16 + c) * 4 + g];
        vo[n][z] = acc;
    }
    __syncthreads();

    // MVLayerNorm
    for (int idx = tid; idx < TN * 16; idx += 128) {
        int n = idx >> 4, c = idx & 15;
        float acc = 0.f;
        #pragma unroll
        for (int bl = 0; bl < 8; bl++) { float x = vo[n][c * 8 + bl]; acc += x * x; }
        cn[n][c] = sqrtf(acc);
    }
    __syncthreads();
    if (tid < TN) {
        float acc = 0.f;
        #pragma unroll
        for (int c = 0; c < 16; c++) acc += cn[tid][c];
        nrm[tid] = acc * (1.f / 16.f) + 1e-6f;
    }
    __syncthreads();
    for (int idx = tid; idx < TN * 128; idx += 128) {
        int n = idx >> 7, z = idx & 127, c = z >> 3;
        out_v[(n0 + n) * 128 + z] = lna[c] * vo[n][z] / nrm[n] + v[(n0 + n) * 128 + z];
    }
}

// ---------------- launcher ----------------
extern "C" void kernel_launch(void* const* d_in, const int* in_sizes, int n_in,
                              void* d_out, int out_size) {
    const float* s     = (const float*)d_in[0];
    const float* v     = (const float*)d_in[1];
    const int*   ei    = (const int*)  d_in[2];
    const float* Wv_w  = (const float*)d_in[3];
    const float* Wv_b  = (const float*)d_in[4];
    const float* mn_W1 = (const float*)d_in[5];
    const float* mn_b1 = (const float*)d_in[6];
    const float* mn_W2 = (const float*)d_in[7];
    const float* mn_b2 = (const float*)d_in[8];
    const float* pn_W1 = (const float*)d_in[9];
    const float* pn_b1 = (const float*)d_in[10];
    const float* pn_W2 = (const float*)d_in[11];
    const float* pn_b2 = (const float*)d_in[12];
    const float* un_W1 = (const float*)d_in[13];
    const float* un_b1 = (const float*)d_in[14];
    const float* un_W2 = (const float*)d_in[15];
    const float* un_b2 = (const float*)d_in[16];
    const float* gl_w  = (const float*)d_in[17];
    const float* gl_b  = (const float*)d_in[18];
    const float* gr_w  = (const float*)d_in[19];
    const float* gr_b  = (const float*)d_in[20];
    const float* go_w  = (const float*)d_in[21];
    const float* go_b  = (const float*)d_in[22];
    const float* ln_a  = (const float*)d_in[23];
    float* out = (float*)d_out;

    zero_kernel<<<4096, 256>>>();
    edge_kernel<<<Ee / TBE, 128>>>(s, v, ei, Wv_w, Wv_b,
                                   mn_W1, mn_b1, mn_W2, mn_b2,
                                   pn_W1, pn_b1, pn_W2, pn_b2);
    node_kernel<<<Nn / TN, 128>>>(s, v, un_W1, un_b1, un_W2, un_b2,
                                  gl_w, gl_b, gr_w, gr_b, go_w, go_b, ln_a,
                                  out, out + Nn * NSc);
}

// round 5
// speedup vs baseline: 1.2462x; 1.2462x over previous
#include <cuda_runtime.h>
#include <cuda_bf16.h>
#include <cstdint>

#define Nn 20000
#define Ee 320000
#define TBE 16
#define TN  8

// ---------------- scratch (device globals; no allocation) ----------------
__device__ float g_maggr[Nn * 128];
__device__ float g_paggr[Nn * 128];
__device__ float g_deg[Nn];
__device__ float g_vij[Ee * 128];
__device__ __nv_bfloat16 g_Shi[Nn * 128], g_Slo[Nn * 128];
__device__ __nv_bfloat16 g_EAhi[Ee * 64], g_EAlo[Ee * 64];
__device__ __nv_bfloat16 g_H1hi[(size_t)Ee * 128], g_H1lo[(size_t)Ee * 128];
__device__ __nv_bfloat16 g_Mhi[(size_t)Ee * 128], g_Mlo[(size_t)Ee * 128];
__device__ __nv_bfloat16 g_W1Thi[128 * 320], g_W1Tlo[128 * 320];
__device__ __nv_bfloat16 g_W2Thi[128 * 128], g_W2Tlo[128 * 128];
__device__ __nv_bfloat16 g_P1Thi[128 * 128], g_P1Tlo[128 * 128];

__constant__ int c_grade[8] = {0, 1, 1, 1, 2, 2, 2, 3};
__device__ constexpr int RES[8][8] = {
    {0,1,2,3,4,5,6,7},{1,0,4,5,2,3,7,6},{2,4,0,6,1,7,3,5},{3,5,6,0,7,1,2,4},
    {4,2,1,7,0,6,5,3},{5,3,7,1,6,0,4,2},{6,7,3,2,5,4,0,1},{7,6,5,4,3,2,1,0}};
__device__ constexpr float SGN[8][8] = {
    { 1, 1, 1, 1, 1, 1, 1, 1},{ 1, 1, 1, 1, 1, 1, 1, 1},
    { 1,-1, 1, 1,-1,-1, 1,-1},{ 1,-1,-1, 1, 1,-1,-1, 1},
    { 1,-1, 1, 1,-1,-1, 1,-1},{ 1,-1,-1, 1, 1,-1,-1, 1},
    { 1, 1,-1, 1,-1, 1,-1,-1},{ 1, 1,-1, 1,-1, 1,-1,-1}};

// ---------------- helpers ----------------
__device__ __forceinline__ uint32_t smem_u32(const void* p) {
    uint32_t a;
    asm("{ .reg .u64 t; cvta.to.shared.u64 t, %1; cvt.u32.u64 %0, t; }" : "=r"(a) : "l"(p));
    return a;
}

// 2 logical 64B rows packed per 128B physical row, SW128 XOR swizzle.
__device__ __forceinline__ uint32_t sw_off(int row, int kb) {
    uint32_t o = ((uint32_t)(row >> 1) << 7) | ((uint32_t)(row & 1) << 6) | (uint32_t)kb;
    return o ^ ((o >> 3) & 0x70);
}

__device__ __forceinline__ void ldsm_x4(uint32_t* r, uint32_t addr) {
    asm volatile("ldmatrix.sync.aligned.m8n8.x4.shared.b16 {%0,%1,%2,%3}, [%4];"
                 : "=r"(r[0]), "=r"(r[1]), "=r"(r[2]), "=r"(r[3]) : "r"(addr));
}
__device__ __forceinline__ void ldsm_x2(uint32_t* r, uint32_t addr) {
    asm volatile("ldmatrix.sync.aligned.m8n8.x2.shared.b16 {%0,%1}, [%2];"
                 : "=r"(r[0]), "=r"(r[1]) : "r"(addr));
}
__device__ __forceinline__ void mma16816(float* c, const uint32_t* a, const uint32_t* b) {
    asm volatile("mma.sync.aligned.m16n8k16.row.col.f32.bf16.bf16.f32 "
                 "{%0,%1,%2,%3}, {%4,%5,%6,%7}, {%8,%9}, {%0,%1,%2,%3};"
                 : "+f"(c[0]), "+f"(c[1]), "+f"(c[2]), "+f"(c[3])
                 : "r"(a[0]), "r"(a[1]), "r"(a[2]), "r"(a[3]), "r"(b[0]), "r"(b[1]));
}

__device__ __forceinline__ void split_bf16(float x, __nv_bfloat16& h, __nv_bfloat16& l) {
    h = __float2bfloat16(x);
    l = __float2bfloat16(x - __bfloat162float(h));
}
__device__ __forceinline__ void store2(__nv_bfloat16* hi, __nv_bfloat16* lo,
                                       size_t off, float x0, float x1) {
    union { __nv_bfloat16 b[2]; uint32_t u; } ph, pl;
    split_bf16(x0, ph.b[0], pl.b[0]);
    split_bf16(x1, ph.b[1], pl.b[1]);
    *(uint32_t*)(hi + off) = ph.u;
    *(uint32_t*)(lo + off) = pl.u;
}

// ---------------- kernel 0: zero scratch ----------------
__global__ __launch_bounds__(256) void zero_kernel() {
    const int tot = Nn * 128 + Nn * 128 + Nn;
    for (int i = blockIdx.x * blockDim.x + threadIdx.x; i < tot; i += gridDim.x * blockDim.x) {
        if (i < Nn * 128) g_maggr[i] = 0.f;
        else if (i < 2 * Nn * 128) g_paggr[i - Nn * 128] = 0.f;
        else g_deg[i - 2 * Nn * 128] = 0.f;
    }
}

// ---------------- kernel 1: split s + transpose/split weights ----------------
__global__ __launch_bounds__(256) void prep_kernel(
    const float* __restrict__ s, const float* __restrict__ W1,
    const float* __restrict__ W2, const float* __restrict__ P1)
{
    const int R0 = Nn * 128, R1 = 128 * 320, R2 = 128 * 128, R3 = 128 * 128;
    const int T = R0 + R1 + R2 + R3;
    for (int i = blockIdx.x * blockDim.x + threadIdx.x; i < T; i += gridDim.x * blockDim.x) {
        if (i < R0) {
            split_bf16(s[i], g_Shi[i], g_Slo[i]);
        } else if (i < R0 + R1) {
            int j = i - R0, n = j / 320, k = j % 320;
            float w = (k < 272) ? W1[k * 128 + n] : 0.f;
            split_bf16(w, g_W1Thi[j], g_W1Tlo[j]);
        } else if (i < R0 + R1 + R2) {
            int j = i - R0 - R1, n = j >> 7, k = j & 127;
            split_bf16(W2[k * 128 + n], g_W2Thi[j], g_W2Tlo[j]);
        } else {
            int j = i - R0 - R1 - R2, n = j >> 7, k = j & 127;
            split_bf16(P1[k * 128 + n], g_P1Thi[j], g_P1Tlo[j]);
        }
    }
}

// ---------------- kernel 2: per-edge MVLinear + edge_attr ----------------
__global__ __launch_bounds__(128) void edge_pre_kernel(
    const float* __restrict__ v, const int* __restrict__ ei,
    const float* __restrict__ Wv_w, const float* __restrict__ Wv_b)
{
    __shared__ float bufA[TBE][128];
    __shared__ float vij[TBE][128];
    __shared__ float attr[TBE][16];
    __shared__ float wv[1024], wvb[16];
    __shared__ int snd[TBE], rcv[TBE];

    const int tid = threadIdx.x;
    const int e0 = blockIdx.x * TBE;

    if (tid < TBE) { snd[tid] = ei[e0 + tid]; rcv[tid] = ei[Ee + e0 + tid]; }
    for (int i = tid; i < 1024; i += 128) wv[i] = Wv_w[i];
    if (tid < 16) wvb[tid] = Wv_b[tid];
    __syncthreads();

    for (int idx = tid; idx < TBE * 128; idx += 128) {
        int e = idx >> 7, z = idx & 127;
        bufA[e][z] = v[rcv[e] * 128 + z] - v[snd[e] * 128 + z];
    }
    if (tid < TBE) atomicAdd(&g_deg[snd[tid]], 1.0f);
    __syncthreads();

    for (int idx = tid; idx < TBE * 128; idx += 128) {
        int e = idx >> 7, z = idx & 127, o = z >> 3, bl = z & 7;
        int g = c_grade[bl];
        float acc = (bl == 0) ? wvb[o] : 0.f;
        #pragma unroll
        for (int c = 0; c < 16; c++) acc += bufA[e][c * 8 + bl] * wv[o * 64 + c * 4 + g];
        vij[e][z] = acc;
    }
    __syncthreads();

    for (int idx = tid; idx < TBE * 16; idx += 128) {
        int e = idx >> 4, o = idx & 15;
        float acc = 0.f;
        #pragma unroll
        for (int bl = 0; bl < 8; bl++) { float x = vij[e][o * 8 + bl]; acc += x * x; }
        attr[e][o] = acc;
    }
    __syncthreads();

    for (int idx = tid; idx < TBE * 128; idx += 128) {
        int e = idx >> 7, z = idx & 127;
        g_vij[(size_t)(e0 + e) * 128 + z] = vij[e][z];
    }
    for (int idx = tid; idx < TBE * 64; idx += 128) {
        int e = idx >> 6, z = idx & 63;
        float x = (z < 16) ? attr[e][z] : 0.f;
        __nv_bfloat16 h, l; split_bf16(x, h, l);
        g_EAhi[(size_t)(e0 + e) * 64 + z] = h;
        g_EAlo[(size_t)(e0 + e) * 64 + z] = l;
    }
}

// ---------------- HMMA GEMM kernels ----------------
// CTA: 128 edges (M) x 128 outputs (N). 4 warps, each 32xN.
// A = hi/lo bf16 split of per-edge rows, B = transposed+split weights.
// 3-pass mma: Ahi*Bhi + Ahi*Blo + Alo*Bhi into fp32 acc.
// MODE 1: X(gathered S rows + EA) @ W1T -> relu -> H1     (K=320, 10 chunks)
// MODE 2: H1 @ W2T (+bias) -> m stores + maggr atomics    (K=128, 4 chunks)
// MODE 3: M @ P1T (+bias) -> relu -> pm(128->16) -> paggr (K=128, 4 chunks)
template <int MODE>
__global__ __launch_bounds__(128) void gemm_kernel(
    const int* __restrict__ ei, const float* __restrict__ bias,
    const float* __restrict__ P2, const float* __restrict__ pb2)
{
    __shared__ __align__(128) unsigned char sbuf[32768];  // Ahi|Alo|Bhi|Blo, 8KB each
    __shared__ float sbias[128];
    __shared__ int srcv[128];
    __shared__ float sP2[(MODE == 3) ? 2048 : 1];
    __shared__ float spb2[16];

    const int tid = threadIdx.x;
    const int lane = tid & 31, w = tid >> 5;
    const int grp = lane >> 2, qid = lane & 3;
    const int e0 = blockIdx.x * 128;
    const int erow = e0 + tid;
    const uint32_t sb = smem_u32(sbuf);
    constexpr int NCHUNK = (MODE == 1) ? 10 : 4;

    sbias[tid] = bias[tid];
    srcv[tid] = ei[Ee + erow];
    int snd = 0;
    if (MODE == 1) snd = ei[erow];
    const int rcv_own = srcv[tid];  // own row's rec (valid: written by this thread)
    if (MODE == 3) {
        for (int i = tid; i < 2048; i += 128) sP2[i] = P2[i];
        if (tid < 16) spb2[tid] = pb2[tid];
    }

    float acc[2][16][4];
    #pragma unroll
    for (int mt = 0; mt < 2; mt++)
        #pragma unroll
        for (int n = 0; n < 16; n++)
            #pragma unroll
            for (int q = 0; q < 4; q++) acc[mt][n][q] = 0.f;

    #pragma unroll 1
    for (int c = 0; c < NCHUNK; c++) {
        // ---- stage A/B chunk (32 k each) ----
        const __nv_bfloat16 *pah, *pal, *pbh, *pbl;
        if (MODE == 1) {
            if (c < 8) {
                int node = (c < 4) ? snd : rcv_own;
                int ko = (c & 3) * 32;
                pah = g_Shi + (size_t)node * 128 + ko;
                pal = g_Slo + (size_t)node * 128 + ko;
            } else {
                int ko = (c - 8) * 32;
                pah = g_EAhi + (size_t)erow * 64 + ko;
                pal = g_EAlo + (size_t)erow * 64 + ko;
            }
            pbh = g_W1Thi + (size_t)tid * 320 + c * 32;
            pbl = g_W1Tlo + (size_t)tid * 320 + c * 32;
        } else if (MODE == 2) {
            pah = g_H1hi + (size_t)erow * 128 + c * 32;
            pal = g_H1lo + (size_t)erow * 128 + c * 32;
            pbh = g_W2Thi + (size_t)tid * 128 + c * 32;
            pbl = g_W2Tlo + (size_t)tid * 128 + c * 32;
        } else {
            pah = g_Mhi + (size_t)erow * 128 + c * 32;
            pal = g_Mlo + (size_t)erow * 128 + c * 32;
            pbh = g_P1Thi + (size_t)tid * 128 + c * 32;
            pbl = g_P1Tlo + (size_t)tid * 128 + c * 32;
        }
        __syncthreads();  // previous chunk's mma done before overwrite
        #pragma unroll
        for (int i = 0; i < 4; i++) {
            uint32_t so = sw_off(tid, i * 16);
            *(uint4*)(sbuf + so)         = ((const uint4*)pah)[i];
            *(uint4*)(sbuf + 8192 + so)  = ((const uint4*)pal)[i];
            *(uint4*)(sbuf + 16384 + so) = ((const uint4*)pbh)[i];
            *(uint4*)(sbuf + 24576 + so) = ((const uint4*)pbl)[i];
        }
        __syncthreads();

        // ---- 2 k16 steps ----
        #pragma unroll
        for (int kk = 0; kk < 2; kk++) {
            const int kkb = kk * 32;
            uint32_t Ahi[2][4], Alo[2][4];
            const int arow = w * 32 + (lane & 15);
            const int akb = kkb + ((lane >> 4) << 4);
            ldsm_x4(Ahi[0], sb + sw_off(arow, akb));
            ldsm_x4(Ahi[1], sb + sw_off(arow + 16, akb));
            ldsm_x4(Alo[0], sb + 8192 + sw_off(arow, akb));
            ldsm_x4(Alo[1], sb + 8192 + sw_off(arow + 16, akb));
            #pragma unroll
            for (int n = 0; n < 16; n++) {
                uint32_t bh[2], bl[2];
                const int brow = n * 8 + (lane & 7);
                const int bkb = kkb + ((lane & 8) ? 16 : 0);
                ldsm_x2(bh, sb + 16384 + sw_off(brow, bkb));
                ldsm_x2(bl, sb + 24576 + sw_off(brow, bkb));
                #pragma unroll
                for (int mt = 0; mt < 2; mt++) {
                    mma16816(acc[mt][n], Ahi[mt], bh);
                    mma16816(acc[mt][n], Ahi[mt], bl);
                    mma16816(acc[mt][n], Alo[mt], bh);
                }
            }
        }
    }
    __syncthreads();

    // ---- epilogue ----
    if (MODE == 1) {
        #pragma unroll
        for (int mt = 0; mt < 2; mt++) {
            int lr0 = w * 32 + mt * 16 + grp;
            #pragma unroll
            for (int n = 0; n < 16; n++) {
                int cc = n * 8 + qid * 2;
                float b0 = sbias[cc], b1 = sbias[cc + 1];
                store2(g_H1hi, g_H1lo, (size_t)(e0 + lr0) * 128 + cc,
                       fmaxf(acc[mt][n][0] + b0, 0.f), fmaxf(acc[mt][n][1] + b1, 0.f));
                store2(g_H1hi, g_H1lo, (size_t)(e0 + lr0 + 8) * 128 + cc,
                       fmaxf(acc[mt][n][2] + b0, 0.f), fmaxf(acc[mt][n][3] + b1, 0.f));
            }
        }
    } else if (MODE == 2) {
        #pragma unroll
        for (int mt = 0; mt < 2; mt++) {
            int lr0 = w * 32 + mt * 16 + grp;
            int r0 = srcv[lr0], r1 = srcv[lr0 + 8];
            #pragma unroll
            for (int n = 0; n < 16; n++) {
                int cc = n * 8 + qid * 2;
                float b0 = sbias[cc], b1 = sbias[cc + 1];
                float x0 = acc[mt][n][0] + b0, x1 = acc[mt][n][1] + b1;
                float x2 = acc[mt][n][2] + b0, x3 = acc[mt][n][3] + b1;
                store2(g_Mhi, g_Mlo, (size_t)(e0 + lr0) * 128 + cc, x0, x1);
                store2(g_Mhi, g_Mlo, (size_t)(e0 + lr0 + 8) * 128 + cc, x2, x3);
                atomicAdd(&g_maggr[(size_t)r0 * 128 + cc], x0);
                atomicAdd(&g_maggr[(size_t)r0 * 128 + cc + 1], x1);
                atomicAdd(&g_maggr[(size_t)r1 * 128 + cc], x2);
                atomicAdd(&g_maggr[(size_t)r1 * 128 + cc + 1], x3);
            }
        }
    } else {
        // relu in place
        #pragma unroll
        for (int mt = 0; mt < 2; mt++)
            #pragma unroll
            for (int n = 0; n < 16; n++) {
                int cc = n * 8 + qid * 2;
                acc[mt][n][0] = fmaxf(acc[mt][n][0] + sbias[cc], 0.f);
                acc[mt][n][1] = fmaxf(acc[mt][n][1] + sbias[cc + 1], 0.f);
                acc[mt][n][2] = fmaxf(acc[mt][n][2] + sbias[cc], 0.f);
                acc[mt][n][3] = fmaxf(acc[mt][n][3] + sbias[cc + 1], 0.f);
            }
        // per-row pm (16) via quad shuffle-reduce, then paggr scatter
        #pragma unroll
        for (int ridx = 0; ridx < 4; ridx++) {
            const int mt = ridx >> 1, half = ridx & 1;
            const int lr = w * 32 + mt * 16 + grp + half * 8;
            float pm[16];
            #pragma unroll
            for (int o = 0; o < 16; o++) pm[o] = 0.f;
            #pragma unroll
            for (int n = 0; n < 16; n++) {
                int cc = n * 8 + qid * 2;
                float x0 = acc[mt][n][half * 2], x1 = acc[mt][n][half * 2 + 1];
                const float* w0 = sP2 + cc * 16;
                const float* w1 = sP2 + (cc + 1) * 16;
                #pragma unroll
                for (int o = 0; o < 16; o++) pm[o] += x0 * w0[o] + x1 * w1[o];
            }
            #pragma unroll
            for (int o = 0; o < 16; o++) {
                pm[o] += __shfl_xor_sync(0xffffffffu, pm[o], 1);
                pm[o] += __shfl_xor_sync(0xffffffffu, pm[o], 2);
                pm[o] += spb2[o];
            }
            const int rc = srcv[lr];
            const float* vr = g_vij + (size_t)(e0 + lr) * 128;
            #pragma unroll 2
            for (int z = qid * 32; z < qid * 32 + 32; z += 4) {
                float4 vv = *(const float4*)(vr + z);
                float p = pm[z >> 3];
                atomicAdd(&g_paggr[(size_t)rc * 128 + z + 0], vv.x * p);
                atomicAdd(&g_paggr[(size_t)rc * 128 + z + 1], vv.y * p);
                atomicAdd(&g_paggr[(size_t)rc * 128 + z + 2], vv.z * p);
                atomicAdd(&g_paggr[(size_t)rc * 128 + z + 3], vv.w * p);
            }
        }
    }
}

// ---------------- kernel: per-node update (unchanged from R3) ----------------
__global__ __launch_bounds__(128) void node_kernel(
    const float* __restrict__ s, const float* __restrict__ v,
    const float* __restrict__ U1, const float* __restrict__ ub1,
    const float* __restrict__ U2, const float* __restrict__ ub2,
    const float* __restrict__ gl_w, const float* __restrict__ gl_b,
    const float* __restrict__ gr_w, const float* __restrict__ gr_b,
    const float* __restrict__ go_w, const float* __restrict__ go_b,
    const float* __restrict__ ln_a,
    float* __restrict__ out_s, float* __restrict__ out_v)
{
    __shared__ __align__(16) float y[TN][256];
    __shared__ __align__(16) float h[TN][128];
    __shared__ __align__(16) float p[TN][128];
    __shared__ __align__(16) float vo[TN][128];
    __shared__ float cn[TN][16];
    __shared__ float nrm[TN];
    __shared__ float dinv[TN];
    __shared__ float wl[1024], wr[1024], wo[2048];
    __shared__ float wlb[16], wrb[16], wob[16], lna[16];

    const int tid = threadIdx.x;
    const int n0 = blockIdx.x * TN;

    for (int i = tid; i < 1024; i += 128) { wl[i] = gl_w[i]; wr[i] = gr_w[i]; }
    for (int i = tid; i < 2048; i += 128) wo[i] = go_w[i];
    if (tid < 16) { wlb[tid] = gl_b[tid]; wrb[tid] = gr_b[tid];
                    wob[tid] = go_b[tid]; lna[tid] = ln_a[tid]; }
    if (tid < TN) dinv[tid] = rsqrtf(g_deg[n0 + tid]);
    __syncthreads();

    for (int idx = tid; idx < TN * 128; idx += 128) {
        int n = idx >> 7, c = idx & 127;
        y[n][c]       = s[(n0 + n) * 128 + c];
        y[n][128 + c] = g_maggr[(n0 + n) * 128 + c] * dinv[n];
        p[n][c]       = g_paggr[(n0 + n) * 128 + c] * dinv[n];
    }
    __syncthreads();

    {
        float acc[TN];
        float bb = ub1[tid];
        #pragma unroll
        for (int n = 0; n < TN; n++) acc[n] = bb;
        for (int k = 0; k < 256; k += 4) {
            float w0 = U1[(k + 0) * 128 + tid];
            float w1 = U1[(k + 1) * 128 + tid];
            float w2 = U1[(k + 2) * 128 + tid];
            float w3 = U1[(k + 3) * 128 + tid];
            #pragma unroll
            for (int n = 0; n < TN; n++) {
                float4 x = *(const float4*)&y[n][k];
                acc[n] += x.x * w0 + x.y * w1 + x.z * w2 + x.w * w3;
            }
        }
        #pragma unroll
        for (int n = 0; n < TN; n++) h[n][tid] = fmaxf(acc[n], 0.f);
    }
    __syncthreads();

    {
        float acc[TN];
        float bb = ub2[tid];
        #pragma unroll
        for (int n = 0; n < TN; n++) acc[n] = bb;
        for (int k = 0; k < 128; k += 4) {
            float w0 = U2[(k + 0) * 128 + tid];
            float w1 = U2[(k + 1) * 128 + tid];
            float w2 = U2[(k + 2) * 128 + tid];
            float w3 = U2[(k + 3) * 128 + tid];
            #pragma unroll
            for (int n = 0; n < TN; n++) {
                float4 x = *(const float4*)&h[n][k];
                acc[n] += x.x * w0 + x.y * w1 + x.z * w2 + x.w * w3;
            }
        }
        #pragma unroll
        for (int n = 0; n < TN; n++)
            out_s[(n0 + n) * 128 + tid] = y[n][tid] + acc[n];
    }
    __syncthreads();

    for (int idx = tid; idx < TN * 128; idx += 128) {
        int n = idx >> 7, z = idx & 127, o = z >> 3, bl = z & 7;
        int g = c_grade[bl];
        float al = (bl == 0) ? wlb[o] : 0.f;
        float ar = (bl == 0) ? wrb[o] : 0.f;
        #pragma unroll
        for (int c = 0; c < 16; c++) {
            float pv = p[n][c * 8 + bl];
            al += pv * wl[o * 64 + c * 4 + g];
            ar += pv * wr[o * 64 + c * 4 + g];
        }
        y[n][z] = al;
        y[n][128 + z] = ar;
    }
    __syncthreads();

    for (int idx = tid; idx < TN * 16; idx += 128) {
        int n = idx >> 4, c = idx & 15;
        float a[8], b[8], o8[8];
        #pragma unroll
        for (int i = 0; i < 8; i++) {
            a[i] = y[n][c * 8 + i];
            b[i] = y[n][128 + c * 8 + i];
            o8[i] = 0.f;
        }
        #pragma unroll
        for (int i = 0; i < 8; i++)
            #pragma unroll
            for (int j = 0; j < 8; j++)
                o8[RES[i][j]] += SGN[i][j] * a[i] * b[j];
        #pragma unroll
        for (int k = 0; k < 8; k++) h[n][c * 8 + k] = o8[k];
    }
    __syncthreads();

    for (int idx = tid; idx < TN * 128; idx += 128) {
        int n = idx >> 7, z = idx & 127, o = z >> 3, bl = z & 7;
        int g = c_grade[bl];
        float acc = (bl == 0) ? wob[o] : 0.f;
        #pragma unroll
        for (int c = 0; c < 16; c++)
            acc += h[n][c * 8 + bl] * wo[o * 128 + c * 4 + g];
        #pragma unroll
        for (int c = 0; c < 16; c++)
            acc += p[n][c * 8 + bl] * wo[o * 128 + (16 + c) * 4 + g];
        vo[n][z] = acc;
    }
    __syncthreads();

    for (int idx = tid; idx < TN * 16; idx += 128) {
        int n = idx >> 4, c = idx & 15;
        float acc = 0.f;
        #pragma unroll
        for (int bl = 0; bl < 8; bl++) { float x = vo[n][c * 8 + bl]; acc += x * x; }
        cn[n][c] = sqrtf(acc);
    }
    __syncthreads();
    if (tid < TN) {
        float acc = 0.f;
        #pragma unroll
        for (int c = 0; c < 16; c++) acc += cn[tid][c];
        nrm[tid] = acc * (1.f / 16.f) + 1e-6f;
    }
    __syncthreads();
    for (int idx = tid; idx < TN * 128; idx += 128) {
        int n = idx >> 7, z = idx & 127, c = z >> 3;
        out_v[(n0 + n) * 128 + z] = lna[c] * vo[n][z] / nrm[n] + v[(n0 + n) * 128 + z];
    }
}

// ---------------- launcher ----------------
extern "C" void kernel_launch(void* const* d_in, const int* in_sizes, int n_in,
                              void* d_out, int out_size) {
    const float* s     = (const float*)d_in[0];
    const float* v     = (const float*)d_in[1];
    const int*   ei    = (const int*)  d_in[2];
    const float* Wv_w  = (const float*)d_in[3];
    const float* Wv_b  = (const float*)d_in[4];
    const float* mn_W1 = (const float*)d_in[5];
    const float* mn_b1 = (const float*)d_in[6];
    const float* mn_W2 = (const float*)d_in[7];
    const float* mn_b2 = (const float*)d_in[8];
    const float* pn_W1 = (const float*)d_in[9];
    const float* pn_b1 = (const float*)d_in[10];
    const float* pn_W2 = (const float*)d_in[11];
    const float* pn_b2 = (const float*)d_in[12];
    const float* un_W1 = (const float*)d_in[13];
    const float* un_b1 = (const float*)d_in[14];
    const float* un_W2 = (const float*)d_in[15];
    const float* un_b2 = (const float*)d_in[16];
    const float* gl_w  = (const float*)d_in[17];
    const float* gl_b  = (const float*)d_in[18];
    const float* gr_w  = (const float*)d_in[19];
    const float* gr_b  = (const float*)d_in[20];
    const float* go_w  = (const float*)d_in[21];
    const float* go_b  = (const float*)d_in[22];
    const float* ln_a  = (const float*)d_in[23];
    float* out = (float*)d_out;

    zero_kernel<<<2048, 256>>>();
    prep_kernel<<<2048, 256>>>(s, mn_W1, mn_W2, pn_W1);
    edge_pre_kernel<<<Ee / TBE, 128>>>(v, ei, Wv_w, Wv_b);
    gemm_kernel<1><<<Ee / 128, 128>>>(ei, mn_b1, nullptr, nullptr);
    gemm_kernel<2><<<Ee / 128, 128>>>(ei, mn_b2, nullptr, nullptr);
    gemm_kernel<3><<<Ee / 128, 128>>>(ei, pn_b1, pn_W2, pn_b2);
    node_kernel<<<Nn / TN, 128>>>(s, v, un_W1, un_b1, un_W2, un_b2,
                                  gl_w, gl_b, gr_w, gr_b, go_w, go_b, ln_a,
                                  out, out + Nn * 128);
}

// round 7
// speedup vs baseline: 1.6692x; 1.3394x over previous
#include <cuda_runtime.h>
#include <cuda_bf16.h>
#include <cstdint>

#define Nn 20000
#define Ee 320000
#define TBE 16
#define TN  8

// ---------------- scratch (device globals; no allocation) ----------------
__device__ float g_maggr[Nn * 128];
__device__ float g_paggr[Nn * 128];
__device__ float g_deg[Nn];
__device__ float g_vij[(size_t)Ee * 128];
__device__ __nv_bfloat16 g_Shi[Nn * 128], g_Slo[Nn * 128];
__device__ __nv_bfloat16 g_EAhi[(size_t)Ee * 64], g_EAlo[(size_t)Ee * 64];
__device__ __nv_bfloat16 g_W1Thi[128 * 320], g_W1Tlo[128 * 320];
__device__ __nv_bfloat16 g_W2Thi[128 * 128], g_W2Tlo[128 * 128];
__device__ __nv_bfloat16 g_P1Thi[128 * 128], g_P1Tlo[128 * 128];

__constant__ int c_grade[8] = {0, 1, 1, 1, 2, 2, 2, 3};
__device__ constexpr int RES[8][8] = {
    {0,1,2,3,4,5,6,7},{1,0,4,5,2,3,7,6},{2,4,0,6,1,7,3,5},{3,5,6,0,7,1,2,4},
    {4,2,1,7,0,6,5,3},{5,3,7,1,6,0,4,2},{6,7,3,2,5,4,0,1},{7,6,5,4,3,2,1,0}};
__device__ constexpr float SGN[8][8] = {
    { 1, 1, 1, 1, 1, 1, 1, 1},{ 1, 1, 1, 1, 1, 1, 1, 1},
    { 1,-1, 1, 1,-1,-1, 1,-1},{ 1,-1,-1, 1, 1,-1,-1, 1},
    { 1,-1, 1, 1,-1,-1, 1,-1},{ 1,-1,-1, 1, 1,-1,-1, 1},
    { 1, 1,-1, 1,-1, 1,-1,-1},{ 1, 1,-1, 1,-1, 1,-1,-1}};

// ---------------- helpers ----------------
__device__ __forceinline__ uint32_t smem_u32(const void* p) {
    uint32_t a;
    asm("{ .reg .u64 t; cvta.to.shared.u64 t, %1; cvt.u32.u64 %0, t; }" : "=r"(a) : "l"(p));
    return a;
}
// 2 logical 64B rows packed per 128B physical row, SW128 XOR swizzle (same as R5).
__device__ __forceinline__ uint32_t sw_off(int row, int kb) {
    uint32_t o = ((uint32_t)(row >> 1) << 7) | ((uint32_t)(row & 1) << 6) | (uint32_t)kb;
    return o ^ ((o >> 3) & 0x70);
}
__device__ __forceinline__ void ldsm_x4(uint32_t* r, uint32_t addr) {
    asm volatile("ldmatrix.sync.aligned.m8n8.x4.shared.b16 {%0,%1,%2,%3}, [%4];"
                 : "=r"(r[0]), "=r"(r[1]), "=r"(r[2]), "=r"(r[3]) : "r"(addr));
}
__device__ __forceinline__ void ldsm_x2(uint32_t* r, uint32_t addr) {
    asm volatile("ldmatrix.sync.aligned.m8n8.x2.shared.b16 {%0,%1}, [%2];"
                 : "=r"(r[0]), "=r"(r[1]) : "r"(addr));
}
__device__ __forceinline__ void mma16816(float* c, const uint32_t* a, const uint32_t* b) {
    asm volatile("mma.sync.aligned.m16n8k16.row.col.f32.bf16.bf16.f32 "
                 "{%0,%1,%2,%3}, {%4,%5,%6,%7}, {%8,%9}, {%0,%1,%2,%3};"
                 : "+f"(c[0]), "+f"(c[1]), "+f"(c[2]), "+f"(c[3])
                 : "r"(a[0]), "r"(a[1]), "r"(a[2]), "r"(a[3]), "r"(b[0]), "r"(b[1]));
}
__device__ __forceinline__ void cpa16(uint32_t dst, const void* src) {
    asm volatile("cp.async.cg.shared.global [%0], [%1], 16;" :: "r"(dst), "l"(src));
}
#define CP_COMMIT() asm volatile("cp.async.commit_group;" ::: "memory")
#define CP_WAIT1()  asm volatile("cp.async.wait_group 1;" ::: "memory")
#define CP_WAIT0()  asm volatile("cp.async.wait_group 0;" ::: "memory")

__device__ __forceinline__ void split_bf16(float x, __nv_bfloat16& h, __nv_bfloat16& l) {
    h = __float2bfloat16(x);
    l = __float2bfloat16(x - __bfloat162float(h));
}
__device__ __forceinline__ void sm_store2(void* hiP, void* loP, float x0, float x1) {
    union { __nv_bfloat16 b[2]; uint32_t u; } ph, pl;
    split_bf16(x0, ph.b[0], pl.b[0]);
    split_bf16(x1, ph.b[1], pl.b[1]);
    *(uint32_t*)hiP = ph.u;
    *(uint32_t*)loP = pl.u;
}

// ---------------- kernel 0: zero scratch ----------------
__global__ __launch_bounds__(256) void zero_kernel() {
    const int tot = Nn * 128 + Nn * 128 + Nn;
    for (int i = blockIdx.x * blockDim.x + threadIdx.x; i < tot; i += gridDim.x * blockDim.x) {
        if (i < Nn * 128) g_maggr[i] = 0.f;
        else if (i < 2 * Nn * 128) g_paggr[i - Nn * 128] = 0.f;
        else g_deg[i - 2 * Nn * 128] = 0.f;
    }
}

// ---------------- kernel 1: split s + transpose/split weights ----------------
__global__ __launch_bounds__(256) void prep_kernel(
    const float* __restrict__ s, const float* __restrict__ W1,
    const float* __restrict__ W2, const float* __restrict__ P1)
{
    const int R0 = Nn * 128, R1 = 128 * 320, R2 = 128 * 128, R3 = 128 * 128;
    const int T = R0 + R1 + R2 + R3;
    for (int i = blockIdx.x * blockDim.x + threadIdx.x; i < T; i += gridDim.x * blockDim.x) {
        if (i < R0) {
            split_bf16(s[i], g_Shi[i], g_Slo[i]);
        } else if (i < R0 + R1) {
            int j = i - R0, n = j / 320, k = j % 320;
            float w = (k < 272) ? W1[k * 128 + n] : 0.f;
            split_bf16(w, g_W1Thi[j], g_W1Tlo[j]);
        } else if (i < R0 + R1 + R2) {
            int j = i - R0 - R1, n = j >> 7, k = j & 127;
            split_bf16(W2[k * 128 + n], g_W2Thi[j], g_W2Tlo[j]);
        } else {
            int j = i - R0 - R1 - R2, n = j >> 7, k = j & 127;
            split_bf16(P1[k * 128 + n], g_P1Thi[j], g_P1Tlo[j]);
        }
    }
}

// ---------------- kernel 2: per-edge MVLinear + edge_attr ----------------
__global__ __launch_bounds__(128) void edge_pre_kernel(
    const float* __restrict__ v, const int* __restrict__ ei,
    const float* __restrict__ Wv_w, const float* __restrict__ Wv_b)
{
    __shared__ float bufA[TBE][128];
    __shared__ float vij[TBE][128];
    __shared__ float attr[TBE][16];
    __shared__ float wv[1024], wvb[16];
    __shared__ int snd[TBE], rcv[TBE];

    const int tid = threadIdx.x;
    const int e0 = blockIdx.x * TBE;

    if (tid < TBE) { snd[tid] = ei[e0 + tid]; rcv[tid] = ei[Ee + e0 + tid]; }
    for (int i = tid; i < 1024; i += 128) wv[i] = Wv_w[i];
    if (tid < 16) wvb[tid] = Wv_b[tid];
    __syncthreads();

    for (int idx = tid; idx < TBE * 128; idx += 128) {
        int e = idx >> 7, z = idx & 127;
        bufA[e][z] = v[rcv[e] * 128 + z] - v[snd[e] * 128 + z];
    }
    if (tid < TBE) atomicAdd(&g_deg[snd[tid]], 1.0f);
    __syncthreads();

    for (int idx = tid; idx < TBE * 128; idx += 128) {
        int e = idx >> 7, z = idx & 127, o = z >> 3, bl = z & 7;
        int g = c_grade[bl];
        float acc = (bl == 0) ? wvb[o] : 0.f;
        #pragma unroll
        for (int c = 0; c < 16; c++) acc += bufA[e][c * 8 + bl] * wv[o * 64 + c * 4 + g];
        vij[e][z] = acc;
    }
    __syncthreads();

    for (int idx = tid; idx < TBE * 16; idx += 128) {
        int e = idx >> 4, o = idx & 15;
        float acc = 0.f;
        #pragma unroll
        for (int bl = 0; bl < 8; bl++) { float x = vij[e][o * 8 + bl]; acc += x * x; }
        attr[e][o] = acc;
    }
    __syncthreads();

    for (int idx = tid; idx < TBE * 128; idx += 128) {
        int e = idx >> 7, z = idx & 127;
        g_vij[(size_t)(e0 + e) * 128 + z] = vij[e][z];
    }
    for (int idx = tid; idx < TBE * 64; idx += 128) {
        int e = idx >> 6, z = idx & 63;
        float x = (z < 16) ? attr[e][z] : 0.f;
        __nv_bfloat16 h, l; split_bf16(x, h, l);
        g_EAhi[(size_t)(e0 + e) * 64 + z] = h;
        g_EAlo[(size_t)(e0 + e) * 64 + z] = l;
    }
}

// ---------------- fused 3-GEMM edge kernel ----------------
// CTA = 128 edges. 256 threads = 8 warps: rw = w&3 (rows rw*32..+32),
// cw = w>>2 (cols cw*64..+64). acc 32x64 per warp = 64 fp32 regs.
// Phase1: X[128,320] @ W1T -> relu -> H1 (smem, chunked layout)
// Phase2: H1 @ W2T -> m -> maggr atomics; sM overwrites H1 region
// Phase3: sM @ P1T -> relu -> pm(128->16) -> paggr scatter
// 2-stage cp.async ring; stage = [Ahi 8K | Alo 8K | Bhi 8K | Blo 8K].
#define RINGO  0
#define SHMO   65536
#define SP2O   131072
#define SB1O   139264
#define SB2O   139776
#define SB3O   140288
#define SPB2O  140800
#define SSNDO  140864
#define SRCVO  141376
#define FUSED_SMEM 141888

__global__ __launch_bounds__(256, 1) void fused_gemm_kernel(
    const int* __restrict__ ei, const float* __restrict__ b1,
    const float* __restrict__ b2, const float* __restrict__ pb1,
    const float* __restrict__ P2, const float* __restrict__ pb2)
{
    extern __shared__ __align__(128) unsigned char smem[];
    const int tid = threadIdx.x;
    const int lane = tid & 31, w = tid >> 5;
    const int rw = w & 3, cw = w >> 2;
    const int grp = lane >> 2, qid = lane & 3;
    const int e0 = blockIdx.x * 128;
    const uint32_t usm = smem_u32(smem);

    int* ssnd = (int*)(smem + SSNDO);
    int* srcv = (int*)(smem + SRCVO);
    float* sb1 = (float*)(smem + SB1O);
    float* sb2 = (float*)(smem + SB2O);
    float* sb3 = (float*)(smem + SB3O);
    float* sP2 = (float*)(smem + SP2O);
    float* spb2 = (float*)(smem + SPB2O);

    if (tid < 128) {
        ssnd[tid] = ei[e0 + tid];
        srcv[tid] = ei[Ee + e0 + tid];
        sb1[tid] = b1[tid];
        sb2[tid] = b2[tid];
        sb3[tid] = pb1[tid];
    }
    for (int i = tid; i < 2048; i += 256) sP2[i] = P2[i];
    if (tid < 16) spb2[tid] = pb2[tid];
    __syncthreads();

    float acc[2][8][4];

    // prefetch one k32 chunk into ring stage s
    auto prefetch = [&](int phase, int c, int s) {
        const int row = tid >> 1;
        const int kb0 = (tid & 1) * 32;
        const uint32_t st = usm + RINGO + s * 32768;
        const uint32_t so0 = st + sw_off(row, kb0);
        const uint32_t so1 = st + sw_off(row, kb0 + 16);
        if (phase == 1) {
            const char *pah, *pal;
            if (c < 8) {
                int node = (c < 4) ? ssnd[row] : srcv[row];
                size_t off = (size_t)node * 128 + (c & 3) * 32;
                pah = (const char*)(g_Shi + off);
                pal = (const char*)(g_Slo + off);
            } else {
                size_t off = (size_t)(e0 + row) * 64 + (c - 8) * 32;
                pah = (const char*)(g_EAhi + off);
                pal = (const char*)(g_EAlo + off);
            }
            cpa16(so0, pah + kb0);
            cpa16(so1, pah + kb0 + 16);
            cpa16(so0 + 8192, pal + kb0);
            cpa16(so1 + 8192, pal + kb0 + 16);
        }
        const char *pbh, *pbl;
        if (phase == 1) {
            size_t o = (size_t)row * 320 + c * 32;
            pbh = (const char*)(g_W1Thi + o); pbl = (const char*)(g_W1Tlo + o);
        } else if (phase == 2) {
            size_t o = (size_t)row * 128 + c * 32;
            pbh = (const char*)(g_W2Thi + o); pbl = (const char*)(g_W2Tlo + o);
        } else {
            size_t o = (size_t)row * 128 + c * 32;
            pbh = (const char*)(g_P1Thi + o); pbl = (const char*)(g_P1Tlo + o);
        }
        cpa16(so0 + 16384, pbh + kb0);
        cpa16(so1 + 16384, pbh + kb0 + 16);
        cpa16(so0 + 24576, pbl + kb0);
        cpa16(so1 + 24576, pbl + kb0 + 16);
    };

    // one k32 chunk of MMAs (3-pass bf16 split)
    auto chunk_mma = [&](uint32_t aHi, uint32_t aLo, uint32_t bHi, uint32_t bLo) {
        #pragma unroll
        for (int kk = 0; kk < 2; kk++) {
            uint32_t Ahi[2][4], Alo[2][4];
            const int arow = rw * 32 + (lane & 15);
            const int akb = kk * 32 + ((lane >> 4) << 4);
            ldsm_x4(Ahi[0], aHi + sw_off(arow, akb));
            ldsm_x4(Ahi[1], aHi + sw_off(arow + 16, akb));
            ldsm_x4(Alo[0], aLo + sw_off(arow, akb));
            ldsm_x4(Alo[1], aLo + sw_off(arow + 16, akb));
            #pragma unroll
            for (int n = 0; n < 8; n++) {
                uint32_t bh[2], bl[2];
                const int brow = cw * 64 + n * 8 + (lane & 7);
                const int bkb = kk * 32 + ((lane & 8) ? 16 : 0);
                ldsm_x2(bh, bHi + sw_off(brow, bkb));
                ldsm_x2(bl, bLo + sw_off(brow, bkb));
                #pragma unroll
                for (int mt = 0; mt < 2; mt++) {
                    mma16816(acc[mt][n], Ahi[mt], bh);
                    mma16816(acc[mt][n], Ahi[mt], bl);
                    mma16816(acc[mt][n], Alo[mt], bh);
                }
            }
        }
    };

    auto run_phase = [&](int phase, int NC, bool aRing) {
        #pragma unroll
        for (int mt = 0; mt < 2; mt++)
            #pragma unroll
            for (int n = 0; n < 8; n++)
                #pragma unroll
                for (int q = 0; q < 4; q++) acc[mt][n][q] = 0.f;
        prefetch(phase, 0, 0);
        CP_COMMIT();
        for (int c = 0; c < NC; c++) {
            if (c + 1 < NC) { prefetch(phase, c + 1, (c + 1) & 1); CP_COMMIT(); CP_WAIT1(); }
            else CP_WAIT0();
            __syncthreads();
            const uint32_t st = usm + RINGO + (c & 1) * 32768;
            const uint32_t aHi = aRing ? st : (usm + SHMO + c * 16384);
            chunk_mma(aHi, aHi + 8192, st + 16384, st + 24576);
            __syncthreads();
        }
    };

    // ================= phase 1 =================
    run_phase(1, 10, true);
    // epilogue: relu + bias -> split -> sHM (chunked layout)
    #pragma unroll
    for (int mt = 0; mt < 2; mt++) {
        const int r0 = rw * 32 + mt * 16 + grp;
        #pragma unroll
        for (int n = 0; n < 8; n++) {
            const int cc = cw * 64 + n * 8 + qid * 2;
            const int ch = cc >> 5;
            const uint32_t kb = (uint32_t)(cc & 31) * 2;
            const float bb0 = sb1[cc], bb1 = sb1[cc + 1];
            unsigned char* base = smem + SHMO + ch * 16384;
            uint32_t o0 = sw_off(r0, kb), o1 = sw_off(r0 + 8, kb);
            sm_store2(base + o0, base + 8192 + o0,
                      fmaxf(acc[mt][n][0] + bb0, 0.f), fmaxf(acc[mt][n][1] + bb1, 0.f));
            sm_store2(base + o1, base + 8192 + o1,
                      fmaxf(acc[mt][n][2] + bb0, 0.f), fmaxf(acc[mt][n][3] + bb1, 0.f));
        }
    }
    __syncthreads();

    // ================= phase 2 =================
    run_phase(2, 4, false);
    // epilogue: m = acc + bias; maggr atomics; write sM into sHM region
    #pragma unroll
    for (int mt = 0; mt < 2; mt++) {
        const int r0 = rw * 32 + mt * 16 + grp;
        const int rA = srcv[r0], rB = srcv[r0 + 8];
        #pragma unroll
        for (int n = 0; n < 8; n++) {
            const int cc = cw * 64 + n * 8 + qid * 2;
            const int ch = cc >> 5;
            const uint32_t kb = (uint32_t)(cc & 31) * 2;
            const float bb0 = sb2[cc], bb1 = sb2[cc + 1];
            float m00 = acc[mt][n][0] + bb0, m01 = acc[mt][n][1] + bb1;
            float m10 = acc[mt][n][2] + bb0, m11 = acc[mt][n][3] + bb1;
            atomicAdd(&g_maggr[(size_t)rA * 128 + cc], m00);
            atomicAdd(&g_maggr[(size_t)rA * 128 + cc + 1], m01);
            atomicAdd(&g_maggr[(size_t)rB * 128 + cc], m10);
            atomicAdd(&g_maggr[(size_t)rB * 128 + cc + 1], m11);
            unsigned char* base = smem + SHMO + ch * 16384;
            uint32_t o0 = sw_off(r0, kb), o1 = sw_off(r0 + 8, kb);
            sm_store2(base + o0, base + 8192 + o0, m00, m01);
            sm_store2(base + o1, base + 8192 + o1, m10, m11);
        }
    }
    __syncthreads();

    // ================= phase 3 =================
    run_phase(3, 4, false);
    // epilogue: relu; per-warp partial pm over this cw half; combine; paggr scatter
    float* spm = (float*)(smem + RINGO);            // [cw][128][16]
    float* spmT = (float*)(smem + RINGO + 16384);   // [128][16]
    #pragma unroll
    for (int mt = 0; mt < 2; mt++) {
        #pragma unroll
        for (int half = 0; half < 2; half++) {
            const int r = rw * 32 + mt * 16 + grp + half * 8;
            float pm[16];
            #pragma unroll
            for (int o = 0; o < 16; o++) pm[o] = 0.f;
            #pragma unroll
            for (int n = 0; n < 8; n++) {
                const int cc = cw * 64 + n * 8 + qid * 2;
                float x0 = fmaxf(acc[mt][n][half * 2 + 0] + sb3[cc], 0.f);
                float x1 = fmaxf(acc[mt][n][half * 2 + 1] + sb3[cc + 1], 0.f);
                const float* w0 = sP2 + cc * 16;
                const float* w1 = w0 + 16;
                #pragma unroll
                for (int o = 0; o < 16; o++) pm[o] += x0 * w0[o] + x1 * w1[o];
            }
            #pragma unroll
            for (int o = 0; o < 16; o++) {
                pm[o] += __shfl_xor_sync(0xffffffffu, pm[o], 1);
                pm[o] += __shfl_xor_sync(0xffffffffu, pm[o], 2);
            }
            #pragma unroll
            for (int j = 0; j < 4; j++)
                spm[cw * 2048 + r * 16 + qid * 4 + j] = pm[qid * 4 + j];
        }
    }
    __syncthreads();
    #pragma unroll
    for (int j = 0; j < 8; j++) {
        const int e = tid + j * 256;
        const int r = e >> 4, o = e & 15;
        spmT[e] = spm[r * 16 + o] + spm[2048 + r * 16 + o] + spb2[o];
    }
    __syncthreads();
    {
        const int r = tid >> 1;
        const int zb = (tid & 1) * 64;
        const int rc = srcv[r];
        const float* vr = g_vij + (size_t)(e0 + r) * 128;
        #pragma unroll 2
        for (int z = zb; z < zb + 64; z += 4) {
            float4 vv = *(const float4*)(vr + z);
            float p = spmT[r * 16 + (z >> 3)];
            atomicAdd(&g_paggr[(size_t)rc * 128 + z + 0], vv.x * p);
            atomicAdd(&g_paggr[(size_t)rc * 128 + z + 1], vv.y * p);
            atomicAdd(&g_paggr[(size_t)rc * 128 + z + 2], vv.z * p);
            atomicAdd(&g_paggr[(size_t)rc * 128 + z + 3], vv.w * p);
        }
    }
}

// ---------------- kernel: per-node update (unchanged from R5) ----------------
__global__ __launch_bounds__(128) void node_kernel(
    const float* __restrict__ s, const float* __restrict__ v,
    const float* __restrict__ U1, const float* __restrict__ ub1,
    const float* __restrict__ U2, const float* __restrict__ ub2,
    const float* __restrict__ gl_w, const float* __restrict__ gl_b,
    const float* __restrict__ gr_w, const float* __restrict__ gr_b,
    const float* __restrict__ go_w, const float* __restrict__ go_b,
    const float* __restrict__ ln_a,
    float* __restrict__ out_s, float* __restrict__ out_v)
{
    __shared__ __align__(16) float y[TN][256];
    __shared__ __align__(16) float h[TN][128];
    __shared__ __align__(16) float p[TN][128];
    __shared__ __align__(16) float vo[TN][128];
    __shared__ float cn[TN][16];
    __shared__ float nrm[TN];
    __shared__ float dinv[TN];
    __shared__ float wl[1024], wr[1024], wo[2048];
    __shared__ float wlb[16], wrb[16], wob[16], lna[16];

    const int tid = threadIdx.x;
    const int n0 = blockIdx.x * TN;

    for (int i = tid; i < 1024; i += 128) { wl[i] = gl_w[i]; wr[i] = gr_w[i]; }
    for (int i = tid; i < 2048; i += 128) wo[i] = go_w[i];
    if (tid < 16) { wlb[tid] = gl_b[tid]; wrb[tid] = gr_b[tid];
                    wob[tid] = go_b[tid]; lna[tid] = ln_a[tid]; }
    if (tid < TN) dinv[tid] = rsqrtf(g_deg[n0 + tid]);
    __syncthreads();

    for (int idx = tid; idx < TN * 128; idx += 128) {
        int n = idx >> 7, c = idx & 127;
        y[n][c]       = s[(n0 + n) * 128 + c];
        y[n][128 + c] = g_maggr[(n0 + n) * 128 + c] * dinv[n];
        p[n][c]       = g_paggr[(n0 + n) * 128 + c] * dinv[n];
    }
    __syncthreads();

    {
        float acc[TN];
        float bb = ub1[tid];
        #pragma unroll
        for (int n = 0; n < TN; n++) acc[n] = bb;
        for (int k = 0; k < 256; k += 4) {
            float w0 = U1[(k + 0) * 128 + tid];
            float w1 = U1[(k + 1) * 128 + tid];
            float w2 = U1[(k + 2) * 128 + tid];
            float w3 = U1[(k + 3) * 128 + tid];
            #pragma unroll
            for (int n = 0; n < TN; n++) {
                float4 x = *(const float4*)&y[n][k];
                acc[n] += x.x * w0 + x.y * w1 + x.z * w2 + x.w * w3;
            }
        }
        #pragma unroll
        for (int n = 0; n < TN; n++) h[n][tid] = fmaxf(acc[n], 0.f);
    }
    __syncthreads();

    {
        float acc[TN];
        float bb = ub2[tid];
        #pragma unroll
        for (int n = 0; n < TN; n++) acc[n] = bb;
        for (int k = 0; k < 128; k += 4) {
            float w0 = U2[(k + 0) * 128 + tid];
            float w1 = U2[(k + 1) * 128 + tid];
            float w2 = U2[(k + 2) * 128 + tid];
            float w3 = U2[(k + 3) * 128 + tid];
            #pragma unroll
            for (int n = 0; n < TN; n++) {
                float4 x = *(const float4*)&h[n][k];
                acc[n] += x.x * w0 + x.y * w1 + x.z * w2 + x.w * w3;
            }
        }
        #pragma unroll
        for (int n = 0; n < TN; n++)
            out_s[(n0 + n) * 128 + tid] = y[n][tid] + acc[n];
    }
    __syncthreads();

    for (int idx = tid; idx < TN * 128; idx += 128) {
        int n = idx >> 7, z = idx & 127, o = z >> 3, bl = z & 7;
        int g = c_grade[bl];
        float al = (bl == 0) ? wlb[o] : 0.f;
        float ar = (bl == 0) ? wrb[o] : 0.f;
        #pragma unroll
        for (int c = 0; c < 16; c++) {
            float pv = p[n][c * 8 + bl];
            al += pv * wl[o * 64 + c * 4 + g];
            ar += pv * wr[o * 64 + c * 4 + g];
        }
        y[n][z] = al;
        y[n][128 + z] = ar;
    }
    __syncthreads();

    for (int idx = tid; idx < TN * 16; idx += 128) {
        int n = idx >> 4, c = idx & 15;
        float a[8], b[8], o8[8];
        #pragma unroll
        for (int i = 0; i < 8; i++) {
            a[i] = y[n][c * 8 + i];
            b[i] = y[n][128 + c * 8 + i];
            o8[i] = 0.f;
        }
        #pragma unroll
        for (int i = 0; i < 8; i++)
            #pragma unroll
            for (int j = 0; j < 8; j++)
                o8[RES[i][j]] += SGN[i][j] * a[i] * b[j];
        #pragma unroll
        for (int k = 0; k < 8; k++) h[n][c * 8 + k] = o8[k];
    }
    __syncthreads();

    for (int idx = tid; idx < TN * 128; idx += 128) {
        int n = idx >> 7, z = idx & 127, o = z >> 3, bl = z & 7;
        int g = c_grade[bl];
        float acc = (bl == 0) ? wob[o] : 0.f;
        #pragma unroll
        for (int c = 0; c < 16; c++)
            acc += h[n][c * 8 + bl] * wo[o * 128 + c * 4 + g];
        #pragma unroll
        for (int c = 0; c < 16; c++)
            acc += p[n][c * 8 + bl] * wo[o * 128 + (16 + c) * 4 + g];
        vo[n][z] = acc;
    }
    __syncthreads();

    for (int idx = tid; idx < TN * 16; idx += 128) {
        int n = idx >> 4, c = idx & 15;
        float acc = 0.f;
        #pragma unroll
        for (int bl = 0; bl < 8; bl++) { float x = vo[n][c * 8 + bl]; acc += x * x; }
        cn[n][c] = sqrtf(acc);
    }
    __syncthreads();
    if (tid < TN) {
        float acc = 0.f;
        #pragma unroll
        for (int c = 0; c < 16; c++) acc += cn[tid][c];
        nrm[tid] = acc * (1.f / 16.f) + 1e-6f;
    }
    __syncthreads();
    for (int idx = tid; idx < TN * 128; idx += 128) {
        int n = idx >> 7, z = idx & 127, c = z >> 3;
        out_v[(n0 + n) * 128 + z] = lna[c] * vo[n][z] / nrm[n] + v[(n0 + n) * 128 + z];
    }
}

// ---------------- launcher ----------------
extern "C" void kernel_launch(void* const* d_in, const int* in_sizes, int n_in,
                              void* d_out, int out_size) {
    const float* s     = (const float*)d_in[0];
    const float* v     = (const float*)d_in[1];
    const int*   ei    = (const int*)  d_in[2];
    const float* Wv_w  = (const float*)d_in[3];
    const float* Wv_b  = (const float*)d_in[4];
    const float* mn_W1 = (const float*)d_in[5];
    const float* mn_b1 = (const float*)d_in[6];
    const float* mn_W2 = (const float*)d_in[7];
    const float* mn_b2 = (const float*)d_in[8];
    const float* pn_W1 = (const float*)d_in[9];
    const float* pn_b1 = (const float*)d_in[10];
    const float* pn_W2 = (const float*)d_in[11];
    const float* pn_b2 = (const float*)d_in[12];
    const float* un_W1 = (const float*)d_in[13];
    const float* un_b1 = (const float*)d_in[14];
    const float* un_W2 = (const float*)d_in[15];
    const float* un_b2 = (const float*)d_in[16];
    const float* gl_w  = (const float*)d_in[17];
    const float* gl_b  = (const float*)d_in[18];
    const float* gr_w  = (const float*)d_in[19];
    const float* gr_b  = (const float*)d_in[20];
    const float* go_w  = (const float*)d_in[21];
    const float* go_b  = (const float*)d_in[22];
    const float* ln_a  = (const float*)d_in[23];
    float* out = (float*)d_out;

    cudaFuncSetAttribute(fused_gemm_kernel,
                         cudaFuncAttributeMaxDynamicSharedMemorySize, FUSED_SMEM);

    zero_kernel<<<2048, 256>>>();
    prep_kernel<<<2048, 256>>>(s, mn_W1, mn_W2, pn_W1);
    edge_pre_kernel<<<Ee / TBE, 128>>>(v, ei, Wv_w, Wv_b);
    fused_gemm_kernel<<<Ee / 128, 256, FUSED_SMEM>>>(ei, mn_b1, mn_b2, pn_b1, pn_W2, pn_b2);
    node_kernel<<<Nn / TN, 128>>>(s, v, un_W1, un_b1, un_W2, un_b2,
                                  gl_w, gl_b, gr_w, gr_b, go_w, go_b, ln_a,
                                  out, out + Nn * 128);
}

// round 9
// speedup vs baseline: 1.7209x; 1.0310x over previous
#include <cuda_runtime.h>
#include <cuda_bf16.h>
#include <cstdint>

#define Nn 20000
#define Ee 320000
#define TBE 16
#define TN  8

// ---------------- scratch (device globals; no allocation) ----------------
__device__ float g_maggr[Nn * 128];
__device__ float g_paggr[Nn * 128];
__device__ float g_deg[Nn];
__device__ float g_vij[(size_t)Ee * 128];
__device__ __nv_bfloat16 g_Shi[Nn * 128], g_Slo[Nn * 128];
__device__ __nv_bfloat16 g_EAhi[(size_t)Ee * 64], g_EAlo[(size_t)Ee * 64];
__device__ __nv_bfloat16 g_W1Thi[128 * 320], g_W1Tlo[128 * 320];
__device__ __nv_bfloat16 g_W2Thi[128 * 128], g_W2Tlo[128 * 128];
__device__ __nv_bfloat16 g_P1Thi[128 * 128], g_P1Tlo[128 * 128];

__constant__ int c_grade[8] = {0, 1, 1, 1, 2, 2, 2, 3};
__device__ constexpr int RES[8][8] = {
    {0,1,2,3,4,5,6,7},{1,0,4,5,2,3,7,6},{2,4,0,6,1,7,3,5},{3,5,6,0,7,1,2,4},
    {4,2,1,7,0,6,5,3},{5,3,7,1,6,0,4,2},{6,7,3,2,5,4,0,1},{7,6,5,4,3,2,1,0}};
__device__ constexpr float SGN[8][8] = {
    { 1, 1, 1, 1, 1, 1, 1, 1},{ 1, 1, 1, 1, 1, 1, 1, 1},
    { 1,-1, 1, 1,-1,-1, 1,-1},{ 1,-1,-1, 1, 1,-1,-1, 1},
    { 1,-1, 1, 1,-1,-1, 1,-1},{ 1,-1,-1, 1, 1,-1,-1, 1},
    { 1, 1,-1, 1,-1, 1,-1,-1},{ 1, 1,-1, 1,-1, 1,-1,-1}};

// ---------------- helpers ----------------
__device__ __forceinline__ uint32_t smem_u32(const void* p) {
    uint32_t a;
    asm("{ .reg .u64 t; cvta.to.shared.u64 t, %1; cvt.u32.u64 %0, t; }" : "=r"(a) : "l"(p));
    return a;
}
// 2 logical 64B rows packed per 128B physical row, SW128 XOR swizzle.
__device__ __forceinline__ uint32_t sw_off(int row, int kb) {
    uint32_t o = ((uint32_t)(row >> 1) << 7) | ((uint32_t)(row & 1) << 6) | (uint32_t)kb;
    return o ^ ((o >> 3) & 0x70);
}
__device__ __forceinline__ void ldsm_x4(uint32_t* r, uint32_t addr) {
    asm volatile("ldmatrix.sync.aligned.m8n8.x4.shared.b16 {%0,%1,%2,%3}, [%4];"
                 : "=r"(r[0]), "=r"(r[1]), "=r"(r[2]), "=r"(r[3]) : "r"(addr));
}
__device__ __forceinline__ void ldsm_x2(uint32_t* r, uint32_t addr) {
    asm volatile("ldmatrix.sync.aligned.m8n8.x2.shared.b16 {%0,%1}, [%2];"
                 : "=r"(r[0]), "=r"(r[1]) : "r"(addr));
}
__device__ __forceinline__ void mma16816(float* c, const uint32_t* a, const uint32_t* b) {
    asm volatile("mma.sync.aligned.m16n8k16.row.col.f32.bf16.bf16.f32 "
                 "{%0,%1,%2,%3}, {%4,%5,%6,%7}, {%8,%9}, {%0,%1,%2,%3};"
                 : "+f"(c[0]), "+f"(c[1]), "+f"(c[2]), "+f"(c[3])
                 : "r"(a[0]), "r"(a[1]), "r"(a[2]), "r"(a[3]), "r"(b[0]), "r"(b[1]));
}
__device__ __forceinline__ void cpa16(uint32_t dst, const void* src) {
    asm volatile("cp.async.cg.shared.global [%0], [%1], 16;" :: "r"(dst), "l"(src));
}
#define CP_COMMIT() asm volatile("cp.async.commit_group;" ::: "memory")
#define CP_WAITG(n) asm volatile("cp.async.wait_group %0;" :: "n"(n) : "memory")

__device__ __forceinline__ void split_bf16(float x, __nv_bfloat16& h, __nv_bfloat16& l) {
    h = __float2bfloat16(x);
    l = __float2bfloat16(x - __bfloat162float(h));
}
__device__ __forceinline__ void sm_store2(void* hiP, void* loP, float x0, float x1) {
    union { __nv_bfloat16 b[2]; uint32_t u; } ph, pl;
    split_bf16(x0, ph.b[0], pl.b[0]);
    split_bf16(x1, ph.b[1], pl.b[1]);
    *(uint32_t*)hiP = ph.u;
    *(uint32_t*)loP = pl.u;
}

// ---------------- kernel 0: zero scratch ----------------
__global__ __launch_bounds__(256) void zero_kernel() {
    const int tot = Nn * 128 + Nn * 128 + Nn;
    for (int i = blockIdx.x * blockDim.x + threadIdx.x; i < tot; i += gridDim.x * blockDim.x) {
        if (i < Nn * 128) g_maggr[i] = 0.f;
        else if (i < 2 * Nn * 128) g_paggr[i - Nn * 128] = 0.f;
        else g_deg[i - 2 * Nn * 128] = 0.f;
    }
}

// ---------------- kernel 1: split s + transpose/split weights ----------------
__global__ __launch_bounds__(256) void prep_kernel(
    const float* __restrict__ s, const float* __restrict__ W1,
    const float* __restrict__ W2, const float* __restrict__ P1)
{
    const int R0 = Nn * 128, R1 = 128 * 320, R2 = 128 * 128, R3 = 128 * 128;
    const int T = R0 + R1 + R2 + R3;
    for (int i = blockIdx.x * blockDim.x + threadIdx.x; i < T; i += gridDim.x * blockDim.x) {
        if (i < R0) {
            split_bf16(s[i], g_Shi[i], g_Slo[i]);
        } else if (i < R0 + R1) {
            int j = i - R0, n = j / 320, k = j % 320;
            float w = (k < 272) ? W1[k * 128 + n] : 0.f;
            split_bf16(w, g_W1Thi[j], g_W1Tlo[j]);
        } else if (i < R0 + R1 + R2) {
            int j = i - R0 - R1, n = j >> 7, k = j & 127;
            split_bf16(W2[k * 128 + n], g_W2Thi[j], g_W2Tlo[j]);
        } else {
            int j = i - R0 - R1 - R2, n = j >> 7, k = j & 127;
            split_bf16(P1[k * 128 + n], g_P1Thi[j], g_P1Tlo[j]);
        }
    }
}

// ---------------- kernel 2: per-edge MVLinear + edge_attr ----------------
__global__ __launch_bounds__(128) void edge_pre_kernel(
    const float* __restrict__ v, const int* __restrict__ ei,
    const float* __restrict__ Wv_w, const float* __restrict__ Wv_b)
{
    __shared__ float bufA[TBE][128];
    __shared__ float vij[TBE][128];
    __shared__ float attr[TBE][16];
    __shared__ float wv[1024], wvb[16];
    __shared__ int snd[TBE], rcv[TBE];

    const int tid = threadIdx.x;
    const int e0 = blockIdx.x * TBE;

    if (tid < TBE) { snd[tid] = ei[e0 + tid]; rcv[tid] = ei[Ee + e0 + tid]; }
    for (int i = tid; i < 1024; i += 128) wv[i] = Wv_w[i];
    if (tid < 16) wvb[tid] = Wv_b[tid];
    __syncthreads();

    for (int idx = tid; idx < TBE * 128; idx += 128) {
        int e = idx >> 7, z = idx & 127;
        bufA[e][z] = v[rcv[e] * 128 + z] - v[snd[e] * 128 + z];
    }
    if (tid < TBE) atomicAdd(&g_deg[snd[tid]], 1.0f);
    __syncthreads();

    for (int idx = tid; idx < TBE * 128; idx += 128) {
        int e = idx >> 7, z = idx & 127, o = z >> 3, bl = z & 7;
        int g = c_grade[bl];
        float acc = (bl == 0) ? wvb[o] : 0.f;
        #pragma unroll
        for (int c = 0; c < 16; c++) acc += bufA[e][c * 8 + bl] * wv[o * 64 + c * 4 + g];
        vij[e][z] = acc;
    }
    __syncthreads();

    for (int idx = tid; idx < TBE * 16; idx += 128) {
        int e = idx >> 4, o = idx & 15;
        float acc = 0.f;
        #pragma unroll
        for (int bl = 0; bl < 8; bl++) { float x = vij[e][o * 8 + bl]; acc += x * x; }
        attr[e][o] = acc;
    }
    __syncthreads();

    for (int idx = tid; idx < TBE * 128; idx += 128) {
        int e = idx >> 7, z = idx & 127;
        g_vij[(size_t)(e0 + e) * 128 + z] = vij[e][z];
    }
    for (int idx = tid; idx < TBE * 64; idx += 128) {
        int e = idx >> 6, z = idx & 63;
        float x = (z < 16) ? attr[e][z] : 0.f;
        __nv_bfloat16 h, l; split_bf16(x, h, l);
        g_EAhi[(size_t)(e0 + e) * 64 + z] = h;
        g_EAlo[(size_t)(e0 + e) * 64 + z] = l;
    }
}

// ---------------- fused 3-GEMM edge kernel ----------------
// CTA = 128 edges, 512 threads = 16 warps: rw = w&3 (rows rw*32..+32),
// cw = w>>2 (cols cw*32..+32). acc 32x32 per warp = 32 fp32 regs.
// 3-stage cp.async ring; per-chunk order is wait -> syncthreads -> prefetch
// -> mma, so the barrier both publishes chunk c's data and proves all warps
// finished mma(c-1) before its stage is overwritten by prefetch(c+2).
#define RINGO  0
#define SHMO   98304
#define SP2O   163840
#define SB1O   172032
#define SB2O   172544
#define SB3O   173056
#define SPB2O  173568
#define SSNDO  173632
#define SRCVO  174144
#define FUSED_SMEM 174656

__global__ __launch_bounds__(512, 1) void fused_gemm_kernel(
    const int* __restrict__ ei, const float* __restrict__ b1,
    const float* __restrict__ b2, const float* __restrict__ pb1,
    const float* __restrict__ P2, const float* __restrict__ pb2)
{
    extern __shared__ __align__(128) unsigned char smem[];
    const int tid = threadIdx.x;
    const int lane = tid & 31, w = tid >> 5;
    const int rw = w & 3, cw = w >> 2;
    const int grp = lane >> 2, qid = lane & 3;
    const int e0 = blockIdx.x * 128;
    const uint32_t usm = smem_u32(smem);

    int* ssnd = (int*)(smem + SSNDO);
    int* srcv = (int*)(smem + SRCVO);
    float* sb1 = (float*)(smem + SB1O);
    float* sb2 = (float*)(smem + SB2O);
    float* sb3 = (float*)(smem + SB3O);
    float* sP2 = (float*)(smem + SP2O);
    float* spb2 = (float*)(smem + SPB2O);

    if (tid < 128) {
        ssnd[tid] = ei[e0 + tid];
        srcv[tid] = ei[Ee + e0 + tid];
        sb1[tid] = b1[tid];
        sb2[tid] = b2[tid];
        sb3[tid] = pb1[tid];
    }
    for (int i = tid; i < 2048; i += 512) sP2[i] = P2[i];
    if (tid < 16) spb2[tid] = pb2[tid];
    __syncthreads();

    float acc[2][4][4];

    // prefetch one k32 chunk into ring stage s (each thread: 16B per buffer)
    const int prow = tid >> 2;
    const int pkb = (tid & 3) * 16;
    auto prefetch = [&](int phase, int c, int s) {
        const uint32_t st = usm + RINGO + s * 32768;
        const uint32_t so = st + sw_off(prow, pkb);
        if (phase == 1) {
            const char *pah, *pal;
            if (c < 8) {
                int node = (c < 4) ? ssnd[prow] : srcv[prow];
                size_t off = (size_t)node * 128 + (c & 3) * 32;
                pah = (const char*)(g_Shi + off);
                pal = (const char*)(g_Slo + off);
            } else {
                size_t off = (size_t)(e0 + prow) * 64 + (c - 8) * 32;
                pah = (const char*)(g_EAhi + off);
                pal = (const char*)(g_EAlo + off);
            }
            cpa16(so, pah + pkb);
            cpa16(so + 8192, pal + pkb);
        }
        const char *pbh, *pbl;
        if (phase == 1) {
            size_t o = (size_t)prow * 320 + c * 32;
            pbh = (const char*)(g_W1Thi + o); pbl = (const char*)(g_W1Tlo + o);
        } else if (phase == 2) {
            size_t o = (size_t)prow * 128 + c * 32;
            pbh = (const char*)(g_W2Thi + o); pbl = (const char*)(g_W2Tlo + o);
        } else {
            size_t o = (size_t)prow * 128 + c * 32;
            pbh = (const char*)(g_P1Thi + o); pbl = (const char*)(g_P1Tlo + o);
        }
        cpa16(so + 16384, pbh + pkb);
        cpa16(so + 24576, pbl + pkb);
    };

    // one k32 chunk of MMAs (3-pass bf16 split), 32x32 warp tile
    auto chunk_mma = [&](uint32_t aHi, uint32_t aLo, uint32_t bHi, uint32_t bLo) {
        #pragma unroll
        for (int kk = 0; kk < 2; kk++) {
            uint32_t Ahi[2][4], Alo[2][4];
            const int arow = rw * 32 + (lane & 15);
            const int akb = kk * 32 + ((lane >> 4) << 4);
            ldsm_x4(Ahi[0], aHi + sw_off(arow, akb));
            ldsm_x4(Ahi[1], aHi + sw_off(arow + 16, akb));
            ldsm_x4(Alo[0], aLo + sw_off(arow, akb));
            ldsm_x4(Alo[1], aLo + sw_off(arow + 16, akb));
            #pragma unroll
            for (int n = 0; n < 4; n++) {
                uint32_t bh[2], bl[2];
                const int brow = cw * 32 + n * 8 + (lane & 7);
                const int bkb = kk * 32 + ((lane & 8) ? 16 : 0);
                ldsm_x2(bh, bHi + sw_off(brow, bkb));
                ldsm_x2(bl, bLo + sw_off(brow, bkb));
                #pragma unroll
                for (int mt = 0; mt < 2; mt++) {
                    mma16816(acc[mt][n], Ahi[mt], bh);
                    mma16816(acc[mt][n], Ahi[mt], bl);
                    mma16816(acc[mt][n], Alo[mt], bh);
                }
            }
        }
    };

    auto run_phase = [&](int phase, int NC, bool aRing) {
        #pragma unroll
        for (int mt = 0; mt < 2; mt++)
            #pragma unroll
            for (int n = 0; n < 4; n++)
                #pragma unroll
                for (int q = 0; q < 4; q++) acc[mt][n][q] = 0.f;
        prefetch(phase, 0, 0); CP_COMMIT();
        prefetch(phase, 1, 1); CP_COMMIT();
        #pragma unroll 1
        for (int c = 0; c < NC; c++) {
            if (c + 1 < NC) CP_WAITG(1);
            else CP_WAITG(0);
            // Publishes chunk c's cp.async data to all warps AND guarantees
            // every warp finished chunk_mma(c-1) — making it safe to overwrite
            // stage (c+2)%3 == (c-1)%3 below.
            __syncthreads();
            if (c + 2 < NC) { prefetch(phase, c + 2, (c + 2) % 3); CP_COMMIT(); }
            const uint32_t st = usm + RINGO + (c % 3) * 32768;
            const uint32_t aHi = aRing ? st : (usm + SHMO + c * 16384);
            chunk_mma(aHi, aHi + 8192, st + 16384, st + 24576);
        }
    };

    // ================= phase 1 =================
    run_phase(1, 10, true);
    // epilogue: relu + bias -> split -> sHM (chunked layout). sHM not read by
    // phase-1 mma, so no barrier needed before these writes.
    #pragma unroll
    for (int mt = 0; mt < 2; mt++) {
        const int r0 = rw * 32 + mt * 16 + grp;
        #pragma unroll
        for (int n = 0; n < 4; n++) {
            const int cc = cw * 32 + n * 8 + qid * 2;
            const int ch = cc >> 5;
            const uint32_t kb = (uint32_t)(cc & 31) * 2;
            const float bb0 = sb1[cc], bb1 = sb1[cc + 1];
            unsigned char* base = smem + SHMO + ch * 16384;
            uint32_t o0 = sw_off(r0, kb), o1 = sw_off(r0 + 8, kb);
            sm_store2(base + o0, base + 8192 + o0,
                      fmaxf(acc[mt][n][0] + bb0, 0.f), fmaxf(acc[mt][n][1] + bb1, 0.f));
            sm_store2(base + o1, base + 8192 + o1,
                      fmaxf(acc[mt][n][2] + bb0, 0.f), fmaxf(acc[mt][n][3] + bb1, 0.f));
        }
    }
    __syncthreads();

    // ================= phase 2 =================
    run_phase(2, 4, false);
    __syncthreads();  // all warps done reading sHM before sM overwrites it
    #pragma unroll
    for (int mt = 0; mt < 2; mt++) {
        const int r0 = rw * 32 + mt * 16 + grp;
        const int rA = srcv[r0], rB = srcv[r0 + 8];
        #pragma unroll
        for (int n = 0; n < 4; n++) {
            const int cc = cw * 32 + n * 8 + qid * 2;
            const int ch = cc >> 5;
            const uint32_t kb = (uint32_t)(cc & 31) * 2;
            const float bb0 = sb2[cc], bb1 = sb2[cc + 1];
            float m00 = acc[mt][n][0] + bb0, m01 = acc[mt][n][1] + bb1;
            float m10 = acc[mt][n][2] + bb0, m11 = acc[mt][n][3] + bb1;
            atomicAdd(&g_maggr[(size_t)rA * 128 + cc], m00);
            atomicAdd(&g_maggr[(size_t)rA * 128 + cc + 1], m01);
            atomicAdd(&g_maggr[(size_t)rB * 128 + cc], m10);
            atomicAdd(&g_maggr[(size_t)rB * 128 + cc + 1], m11);
            unsigned char* base = smem + SHMO + ch * 16384;
            uint32_t o0 = sw_off(r0, kb), o1 = sw_off(r0 + 8, kb);
            sm_store2(base + o0, base + 8192 + o0, m00, m01);
            sm_store2(base + o1, base + 8192 + o1, m10, m11);
        }
    }
    __syncthreads();

    // ================= phase 3 =================
    run_phase(3, 4, false);
    __syncthreads();  // all warps done with ring before spm reuses it
    float* spm = (float*)(smem + RINGO);            // [cw][128][16]
    float* spmT = (float*)(smem + RINGO + 32768);   // [128][16]
    #pragma unroll
    for (int mt = 0; mt < 2; mt++) {
        #pragma unroll
        for (int half = 0; half < 2; half++) {
            const int r = rw * 32 + mt * 16 + grp + half * 8;
            float pm[16];
            #pragma unroll
            for (int o = 0; o < 16; o++) pm[o] = 0.f;
            #pragma unroll
            for (int n = 0; n < 4; n++) {
                const int cc = cw * 32 + n * 8 + qid * 2;
                float x0 = fmaxf(acc[mt][n][half * 2 + 0] + sb3[cc], 0.f);
                float x1 = fmaxf(acc[mt][n][half * 2 + 1] + sb3[cc + 1], 0.f);
                const float* w0 = sP2 + cc * 16;
                const float* w1 = w0 + 16;
                #pragma unroll
                for (int o = 0; o < 16; o++) pm[o] += x0 * w0[o] + x1 * w1[o];
            }
            #pragma unroll
            for (int o = 0; o < 16; o++) {
                pm[o] += __shfl_xor_sync(0xffffffffu, pm[o], 1);
                pm[o] += __shfl_xor_sync(0xffffffffu, pm[o], 2);
            }
            #pragma unroll
            for (int j = 0; j < 4; j++)
                spm[cw * 2048 + r * 16 + qid * 4 + j] = pm[qid * 4 + j];
        }
    }
    __syncthreads();
    #pragma unroll
    for (int j = 0; j < 4; j++) {
        const int e = tid + j * 512;
        const int r = e >> 4, o = e & 15;
        spmT[e] = spm[r * 16 + o] + spm[2048 + r * 16 + o]
                + spm[4096 + r * 16 + o] + spm[6144 + r * 16 + o] + spb2[o];
    }
    __syncthreads();
    {
        const int r = tid >> 2;
        const int zb = (tid & 3) * 32;
        const int rc = srcv[r];
        const float* vr = g_vij + (size_t)(e0 + r) * 128;
        #pragma unroll 2
        for (int z = zb; z < zb + 32; z += 4) {
            float4 vv = *(const float4*)(vr + z);
            float p = spmT[r * 16 + (z >> 3)];
            atomicAdd(&g_paggr[(size_t)rc * 128 + z + 0], vv.x * p);
            atomicAdd(&g_paggr[(size_t)rc * 128 + z + 1], vv.y * p);
            atomicAdd(&g_paggr[(size_t)rc * 128 + z + 2], vv.z * p);
            atomicAdd(&g_paggr[(size_t)rc * 128 + z + 3], vv.w * p);
        }
    }
}

// ---------------- kernel: per-node update ----------------
__global__ __launch_bounds__(128) void node_kernel(
    const float* __restrict__ s, const float* __restrict__ v,
    const float* __restrict__ U1, const float* __restrict__ ub1,
    const float* __restrict__ U2, const float* __restrict__ ub2,
    const float* __restrict__ gl_w, const float* __restrict__ gl_b,
    const float* __restrict__ gr_w, const float* __restrict__ gr_b,
    const float* __restrict__ go_w, const float* __restrict__ go_b,
    const float* __restrict__ ln_a,
    float* __restrict__ out_s, float* __restrict__ out_v)
{
    __shared__ __align__(16) float y[TN][256];
    __shared__ __align__(16) float h[TN][128];
    __shared__ __align__(16) float p[TN][128];
    __shared__ __align__(16) float vo[TN][128];
    __shared__ float cn[TN][16];
    __shared__ float nrm[TN];
    __shared__ float dinv[TN];
    __shared__ float wl[1024], wr[1024], wo[2048];
    __shared__ float wlb[16], wrb[16], wob[16], lna[16];

    const int tid = threadIdx.x;
    const int n0 = blockIdx.x * TN;

    for (int i = tid; i < 1024; i += 128) { wl[i] = gl_w[i]; wr[i] = gr_w[i]; }
    for (int i = tid; i < 2048; i += 128) wo[i] = go_w[i];
    if (tid < 16) { wlb[tid] = gl_b[tid]; wrb[tid] = gr_b[tid];
                    wob[tid] = go_b[tid]; lna[tid] = ln_a[tid]; }
    if (tid < TN) dinv[tid] = rsqrtf(g_deg[n0 + tid]);
    __syncthreads();

    for (int idx = tid; idx < TN * 128; idx += 128) {
        int n = idx >> 7, c = idx & 127;
        y[n][c]       = s[(n0 + n) * 128 + c];
        y[n][128 + c] = g_maggr[(n0 + n) * 128 + c] * dinv[n];
        p[n][c]       = g_paggr[(n0 + n) * 128 + c] * dinv[n];
    }
    __syncthreads();

    {
        float acc[TN];
        float bb = ub1[tid];
        #pragma unroll
        for (int n = 0; n < TN; n++) acc[n] = bb;
        for (int k = 0; k < 256; k += 4) {
            float w0 = U1[(k + 0) * 128 + tid];
            float w1 = U1[(k + 1) * 128 + tid];
            float w2 = U1[(k + 2) * 128 + tid];
            float w3 = U1[(k + 3) * 128 + tid];
            #pragma unroll
            for (int n = 0; n < TN; n++) {
                float4 x = *(const float4*)&y[n][k];
                acc[n] += x.x * w0 + x.y * w1 + x.z * w2 + x.w * w3;
            }
        }
        #pragma unroll
        for (int n = 0; n < TN; n++) h[n][tid] = fmaxf(acc[n], 0.f);
    }
    __syncthreads();

    {
        float acc[TN];
        float bb = ub2[tid];
        #pragma unroll
        for (int n = 0; n < TN; n++) acc[n] = bb;
        for (int k = 0; k < 128; k += 4) {
            float w0 = U2[(k + 0) * 128 + tid];
            float w1 = U2[(k + 1) * 128 + tid];
            float w2 = U2[(k + 2) * 128 + tid];
            float w3 = U2[(k + 3) * 128 + tid];
            #pragma unroll
            for (int n = 0; n < TN; n++) {
                float4 x = *(const float4*)&h[n][k];
                acc[n] += x.x * w0 + x.y * w1 + x.z * w2 + x.w * w3;
            }
        }
        #pragma unroll
        for (int n = 0; n < TN; n++)
            out_s[(n0 + n) * 128 + tid] = y[n][tid] + acc[n];
    }
    __syncthreads();

    for (int idx = tid; idx < TN * 128; idx += 128) {
        int n = idx >> 7, z = idx & 127, o = z >> 3, bl = z & 7;
        int g = c_grade[bl];
        float al = (bl == 0) ? wlb[o] : 0.f;
        float ar = (bl == 0) ? wrb[o] : 0.f;
        #pragma unroll
        for (int c = 0; c < 16; c++) {
            float pv = p[n][c * 8 + bl];
            al += pv * wl[o * 64 + c * 4 + g];
            ar += pv * wr[o * 64 + c * 4 + g];
        }
        y[n][z] = al;
        y[n][128 + z] = ar;
    }
    __syncthreads();

    for (int idx = tid; idx < TN * 16; idx += 128) {
        int n = idx >> 4, c = idx & 15;
        float a[8], b[8], o8[8];
        #pragma unroll
        for (int i = 0; i < 8; i++) {
            a[i] = y[n][c * 8 + i];
            b[i] = y[n][128 + c * 8 + i];
            o8[i] = 0.f;
        }
        #pragma unroll
        for (int i = 0; i < 8; i++)
            #pragma unroll
            for (int j = 0; j < 8; j++)
                o8[RES[i][j]] += SGN[i][j] * a[i] * b[j];
        #pragma unroll
        for (int k = 0; k < 8; k++) h[n][c * 8 + k] = o8[k];
    }
    __syncthreads();

    for (int idx = tid; idx < TN * 128; idx += 128) {
        int n = idx >> 7, z = idx & 127, o = z >> 3, bl = z & 7;
        int g = c_grade[bl];
        float acc = (bl == 0) ? wob[o] : 0.f;
        #pragma unroll
        for (int c = 0; c < 16; c++)
            acc += h[n][c * 8 + bl] * wo[o * 128 + c * 4 + g];
        #pragma unroll
        for (int c = 0; c < 16; c++)
            acc += p[n][c * 8 + bl] * wo[o * 128 + (16 + c) * 4 + g];
        vo[n][z] = acc;
    }
    __syncthreads();

    for (int idx = tid; idx < TN * 16; idx += 128) {
        int n = idx >> 4, c = idx & 15;
        float acc = 0.f;
        #pragma unroll
        for (int bl = 0; bl < 8; bl++) { float x = vo[n][c * 8 + bl]; acc += x * x; }
        cn[n][c] = sqrtf(acc);
    }
    __syncthreads();
    if (tid < TN) {
        float acc = 0.f;
        #pragma unroll
        for (int c = 0; c < 16; c++) acc += cn[tid][c];
        nrm[tid] = acc * (1.f / 16.f) + 1e-6f;
    }
    __syncthreads();
    for (int idx = tid; idx < TN * 128; idx += 128) {
        int n = idx >> 7, z = idx & 127, c = z >> 3;
        out_v[(n0 + n) * 128 + z] = lna[c] * vo[n][z] / nrm[n] + v[(n0 + n) * 128 + z];
    }
}

// ---------------- launcher ----------------
extern "C" void kernel_launch(void* const* d_in, const int* in_sizes, int n_in,
                              void* d_out, int out_size) {
    const float* s     = (const float*)d_in[0];
    const float* v     = (const float*)d_in[1];
    const int*   ei    = (const int*)  d_in[2];
    const float* Wv_w  = (const float*)d_in[3];
    const float* Wv_b  = (const float*)d_in[4];
    const float* mn_W1 = (const float*)d_in[5];
    const float* mn_b1 = (const float*)d_in[6];
    const float* mn_W2 = (const float*)d_in[7];
    const float* mn_b2 = (const float*)d_in[8];
    const float* pn_W1 = (const float*)d_in[9];
    const float* pn_b1 = (const float*)d_in[10];
    const float* pn_W2 = (const float*)d_in[11];
    const float* pn_b2 = (const float*)d_in[12];
    const float* un_W1 = (const float*)d_in[13];
    const float* un_b1 = (const float*)d_in[14];
    const float* un_W2 = (const float*)d_in[15];
    const float* un_b2 = (const float*)d_in[16];
    const float* gl_w  = (const float*)d_in[17];
    const float* gl_b  = (const float*)d_in[18];
    const float* gr_w  = (const float*)d_in[19];
    const float* gr_b  = (const float*)d_in[20];
    const float* go_w  = (const float*)d_in[21];
    const float* go_b  = (const float*)d_in[22];
    const float* ln_a  = (const float*)d_in[23];
    float* out = (float*)d_out;

    cudaFuncSetAttribute(fused_gemm_kernel,
                         cudaFuncAttributeMaxDynamicSharedMemorySize, FUSED_SMEM);

    zero_kernel<<<2048, 256>>>();
    prep_kernel<<<2048, 256>>>(s, mn_W1, mn_W2, pn_W1);
    edge_pre_kernel<<<Ee / TBE, 128>>>(v, ei, Wv_w, Wv_b);
    fused_gemm_kernel<<<Ee / 128, 512, FUSED_SMEM>>>(ei, mn_b1, mn_b2, pn_b1, pn_W2, pn_b2);
    node_kernel<<<Nn / TN, 128>>>(s, v, un_W1, un_b1, un_W2, un_b2,
                                  gl_w, gl_b, gr_w, gr_b, go_w, go_b, ln_a,
                                  out, out + Nn * 128);
}

// round 10
// speedup vs baseline: 1.9521x; 1.1344x over previous
#include <cuda_runtime.h>
#include <cuda_bf16.h>
#include <cstdint>

#define Nn 20000
#define Ee 320000
#define TBE 16
#define TN  8

// ---------------- scratch (device globals; no allocation) ----------------
__device__ float g_maggr[Nn * 128];
__device__ float g_paggr[Nn * 128];
__device__ float g_deg[Nn];
__device__ float g_vij[(size_t)Ee * 128];
__device__ __nv_bfloat16 g_Shi[Nn * 128], g_Slo[Nn * 128];
__device__ __nv_bfloat16 g_EAhi[(size_t)Ee * 64], g_EAlo[(size_t)Ee * 64];
__device__ __nv_bfloat16 g_W1Thi[128 * 320], g_W1Tlo[128 * 320];
__device__ __nv_bfloat16 g_W2Thi[128 * 128], g_W2Tlo[128 * 128];
__device__ __nv_bfloat16 g_P1Thi[128 * 128], g_P1Tlo[128 * 128];

__constant__ int c_grade[8] = {0, 1, 1, 1, 2, 2, 2, 3};
__device__ constexpr int RES[8][8] = {
    {0,1,2,3,4,5,6,7},{1,0,4,5,2,3,7,6},{2,4,0,6,1,7,3,5},{3,5,6,0,7,1,2,4},
    {4,2,1,7,0,6,5,3},{5,3,7,1,6,0,4,2},{6,7,3,2,5,4,0,1},{7,6,5,4,3,2,1,0}};
__device__ constexpr float SGN[8][8] = {
    { 1, 1, 1, 1, 1, 1, 1, 1},{ 1, 1, 1, 1, 1, 1, 1, 1},
    { 1,-1, 1, 1,-1,-1, 1,-1},{ 1,-1,-1, 1, 1,-1,-1, 1},
    { 1,-1, 1, 1,-1,-1, 1,-1},{ 1,-1,-1, 1, 1,-1,-1, 1},
    { 1, 1,-1, 1,-1, 1,-1,-1},{ 1, 1,-1, 1,-1, 1,-1,-1}};

// ---------------- helpers ----------------
__device__ __forceinline__ uint32_t smem_u32(const void* p) {
    uint32_t a;
    asm("{ .reg .u64 t; cvta.to.shared.u64 t, %1; cvt.u32.u64 %0, t; }" : "=r"(a) : "l"(p));
    return a;
}
// 2 logical 64B rows packed per 128B physical row, SW128 XOR swizzle.
__device__ __forceinline__ uint32_t sw_off(int row, int kb) {
    uint32_t o = ((uint32_t)(row >> 1) << 7) | ((uint32_t)(row & 1) << 6) | (uint32_t)kb;
    return o ^ ((o >> 3) & 0x70);
}
__device__ __forceinline__ void ldsm_x4(uint32_t* r, uint32_t addr) {
    asm volatile("ldmatrix.sync.aligned.m8n8.x4.shared.b16 {%0,%1,%2,%3}, [%4];"
                 : "=r"(r[0]), "=r"(r[1]), "=r"(r[2]), "=r"(r[3]) : "r"(addr));
}
__device__ __forceinline__ void mma16816(float* c, const uint32_t* a, const uint32_t* b) {
    asm volatile("mma.sync.aligned.m16n8k16.row.col.f32.bf16.bf16.f32 "
                 "{%0,%1,%2,%3}, {%4,%5,%6,%7}, {%8,%9}, {%0,%1,%2,%3};"
                 : "+f"(c[0]), "+f"(c[1]), "+f"(c[2]), "+f"(c[3])
                 : "r"(a[0]), "r"(a[1]), "r"(a[2]), "r"(a[3]), "r"(b[0]), "r"(b[1]));
}
__device__ __forceinline__ void cpa16(uint32_t dst, const void* src) {
    asm volatile("cp.async.cg.shared.global [%0], [%1], 16;" :: "r"(dst), "l"(src));
}
#define CP_COMMIT() asm volatile("cp.async.commit_group;" ::: "memory")
#define CP_WAITG(n) asm volatile("cp.async.wait_group %0;" :: "n"(n) : "memory")

// vectorized global float reductions (PTX ISA 8.1+, sm_90+)
__device__ __forceinline__ void red_add_v4(float* p, float x0, float x1, float x2, float x3) {
    asm volatile("red.global.add.v4.f32 [%0], {%1, %2, %3, %4};"
                 :: "l"(p), "f"(x0), "f"(x1), "f"(x2), "f"(x3) : "memory");
}
__device__ __forceinline__ void red_add_v2(float* p, float x0, float x1) {
    asm volatile("red.global.add.v2.f32 [%0], {%1, %2};"
                 :: "l"(p), "f"(x0), "f"(x1) : "memory");
}

__device__ __forceinline__ void split_bf16(float x, __nv_bfloat16& h, __nv_bfloat16& l) {
    h = __float2bfloat16(x);
    l = __float2bfloat16(x - __bfloat162float(h));
}
__device__ __forceinline__ void sm_store2(void* hiP, void* loP, float x0, float x1) {
    union { __nv_bfloat16 b[2]; uint32_t u; } ph, pl;
    split_bf16(x0, ph.b[0], pl.b[0]);
    split_bf16(x1, ph.b[1], pl.b[1]);
    *(uint32_t*)hiP = ph.u;
    *(uint32_t*)loP = pl.u;
}

// ---------------- kernel 0: zero scratch ----------------
__global__ __launch_bounds__(256) void zero_kernel() {
    const int tot = Nn * 128 + Nn * 128 + Nn;
    for (int i = blockIdx.x * blockDim.x + threadIdx.x; i < tot; i += gridDim.x * blockDim.x) {
        if (i < Nn * 128) g_maggr[i] = 0.f;
        else if (i < 2 * Nn * 128) g_paggr[i - Nn * 128] = 0.f;
        else g_deg[i - 2 * Nn * 128] = 0.f;
    }
}

// ---------------- kernel 1: split s + transpose/split weights ----------------
__global__ __launch_bounds__(256) void prep_kernel(
    const float* __restrict__ s, const float* __restrict__ W1,
    const float* __restrict__ W2, const float* __restrict__ P1)
{
    const int R0 = Nn * 128, R1 = 128 * 320, R2 = 128 * 128, R3 = 128 * 128;
    const int T = R0 + R1 + R2 + R3;
    for (int i = blockIdx.x * blockDim.x + threadIdx.x; i < T; i += gridDim.x * blockDim.x) {
        if (i < R0) {
            split_bf16(s[i], g_Shi[i], g_Slo[i]);
        } else if (i < R0 + R1) {
            int j = i - R0, n = j / 320, k = j % 320;
            float w = (k < 272) ? W1[k * 128 + n] : 0.f;
            split_bf16(w, g_W1Thi[j], g_W1Tlo[j]);
        } else if (i < R0 + R1 + R2) {
            int j = i - R0 - R1, n = j >> 7, k = j & 127;
            split_bf16(W2[k * 128 + n], g_W2Thi[j], g_W2Tlo[j]);
        } else {
            int j = i - R0 - R1 - R2, n = j >> 7, k = j & 127;
            split_bf16(P1[k * 128 + n], g_P1Thi[j], g_P1Tlo[j]);
        }
    }
}

// ---------------- kernel 2: per-edge MVLinear + edge_attr ----------------
__global__ __launch_bounds__(128) void edge_pre_kernel(
    const float* __restrict__ v, const int* __restrict__ ei,
    const float* __restrict__ Wv_w, const float* __restrict__ Wv_b)
{
    __shared__ float bufA[TBE][128];
    __shared__ float vij[TBE][128];
    __shared__ float attr[TBE][16];
    __shared__ float wv[1024], wvb[16];
    __shared__ int snd[TBE], rcv[TBE];

    const int tid = threadIdx.x;
    const int e0 = blockIdx.x * TBE;

    if (tid < TBE) { snd[tid] = ei[e0 + tid]; rcv[tid] = ei[Ee + e0 + tid]; }
    for (int i = tid; i < 1024; i += 128) wv[i] = Wv_w[i];
    if (tid < 16) wvb[tid] = Wv_b[tid];
    __syncthreads();

    for (int idx = tid; idx < TBE * 128; idx += 128) {
        int e = idx >> 7, z = idx & 127;
        bufA[e][z] = v[rcv[e] * 128 + z] - v[snd[e] * 128 + z];
    }
    if (tid < TBE) atomicAdd(&g_deg[snd[tid]], 1.0f);
    __syncthreads();

    for (int idx = tid; idx < TBE * 128; idx += 128) {
        int e = idx >> 7, z = idx & 127, o = z >> 3, bl = z & 7;
        int g = c_grade[bl];
        float acc = (bl == 0) ? wvb[o] : 0.f;
        #pragma unroll
        for (int c = 0; c < 16; c++) acc += bufA[e][c * 8 + bl] * wv[o * 64 + c * 4 + g];
        vij[e][z] = acc;
    }
    __syncthreads();

    for (int idx = tid; idx < TBE * 16; idx += 128) {
        int e = idx >> 4, o = idx & 15;
        float acc = 0.f;
        #pragma unroll
        for (int bl = 0; bl < 8; bl++) { float x = vij[e][o * 8 + bl]; acc += x * x; }
        attr[e][o] = acc;
    }
    __syncthreads();

    for (int idx = tid; idx < TBE * 128; idx += 128) {
        int e = idx >> 7, z = idx & 127;
        g_vij[(size_t)(e0 + e) * 128 + z] = vij[e][z];
    }
    for (int idx = tid; idx < TBE * 64; idx += 128) {
        int e = idx >> 6, z = idx & 63;
        float x = (z < 16) ? attr[e][z] : 0.f;
        __nv_bfloat16 h, l; split_bf16(x, h, l);
        g_EAhi[(size_t)(e0 + e) * 64 + z] = h;
        g_EAlo[(size_t)(e0 + e) * 64 + z] = l;
    }
}

// ---------------- fused 3-GEMM edge kernel ----------------
// CTA = 128 edges, 512 threads = 16 warps: rw = w&3 (rows rw*32..+32),
// cw = w>>2 (cols cw*32..+32). acc 32x32 per warp = 32 fp32 regs.
// Phase 1: 10x 32-k chunks through 3-stage ring (wait->sync->prefetch->mma).
// Phases 2/3: A = sHM; B staged as 2x 64-k chunks (both in flight up front),
// each mma'd as two 32-k sub-chunks -> only 2 barriers per phase.
#define RINGO  0
#define SHMO   98304
#define SP2O   163840
#define SB1O   172032
#define SB2O   172544
#define SB3O   173056
#define SPB2O  173568
#define SSNDO  173632
#define SRCVO  174144
#define FUSED_SMEM 174656

__global__ __launch_bounds__(512, 1) void fused_gemm_kernel(
    const int* __restrict__ ei, const float* __restrict__ b1,
    const float* __restrict__ b2, const float* __restrict__ pb1,
    const float* __restrict__ P2, const float* __restrict__ pb2)
{
    extern __shared__ __align__(128) unsigned char smem[];
    const int tid = threadIdx.x;
    const int lane = tid & 31, w = tid >> 5;
    const int rw = w & 3, cw = w >> 2;
    const int grp = lane >> 2, qid = lane & 3;
    const int e0 = blockIdx.x * 128;
    const uint32_t usm = smem_u32(smem);

    int* ssnd = (int*)(smem + SSNDO);
    int* srcv = (int*)(smem + SRCVO);
    float* sb1 = (float*)(smem + SB1O);
    float* sb2 = (float*)(smem + SB2O);
    float* sb3 = (float*)(smem + SB3O);
    float* sP2 = (float*)(smem + SP2O);
    float* spb2 = (float*)(smem + SPB2O);

    if (tid < 128) {
        ssnd[tid] = ei[e0 + tid];
        srcv[tid] = ei[Ee + e0 + tid];
        sb1[tid] = b1[tid];
        sb2[tid] = b2[tid];
        sb3[tid] = pb1[tid];
    }
    for (int i = tid; i < 2048; i += 512) sP2[i] = P2[i];
    if (tid < 16) spb2[tid] = pb2[tid];
    __syncthreads();

    float acc[2][4][4];

    const int prow = tid >> 2;
    const int pkb = (tid & 3) * 16;

    // phase-1 prefetch: one 32-k chunk (A + B) into ring stage s
    auto prefetch1 = [&](int c, int s) {
        const uint32_t st = usm + RINGO + s * 32768;
        const uint32_t so = st + sw_off(prow, pkb);
        const char *pah, *pal;
        if (c < 8) {
            int node = (c < 4) ? ssnd[prow] : srcv[prow];
            size_t off = (size_t)node * 128 + (c & 3) * 32;
            pah = (const char*)(g_Shi + off);
            pal = (const char*)(g_Slo + off);
        } else {
            size_t off = (size_t)(e0 + prow) * 64 + (c - 8) * 32;
            pah = (const char*)(g_EAhi + off);
            pal = (const char*)(g_EAlo + off);
        }
        cpa16(so, pah + pkb);
        cpa16(so + 8192, pal + pkb);
        size_t o = (size_t)prow * 320 + c * 32;
        cpa16(so + 16384, (const char*)(g_W1Thi + o) + pkb);
        cpa16(so + 24576, (const char*)(g_W1Tlo + o) + pkb);
    };

    // phase-2/3 prefetch: one 64-k B-only chunk into ring stage c
    // layout: stage = [sub0: Bhi 8K | Blo 8K][sub1: Bhi 8K | Blo 8K]
    auto prefetch23 = [&](int phase, int c) {
        const uint32_t st = usm + RINGO + c * 32768;
        const __nv_bfloat16* Whi = (phase == 2) ? g_W2Thi : g_P1Thi;
        const __nv_bfloat16* Wlo = (phase == 2) ? g_W2Tlo : g_P1Tlo;
        #pragma unroll
        for (int sub = 0; sub < 2; sub++) {
            const uint32_t so = st + sub * 16384 + sw_off(prow, pkb);
            size_t o = (size_t)prow * 128 + c * 64 + sub * 32;
            cpa16(so, (const char*)(Whi + o) + pkb);
            cpa16(so + 8192, (const char*)(Wlo + o) + pkb);
        }
    };

    // one 32-k chunk of MMAs (3-pass bf16 split), 32x32 warp tile
    auto chunk_mma = [&](uint32_t aHi, uint32_t aLo, uint32_t bHi, uint32_t bLo) {
        #pragma unroll
        for (int kk = 0; kk < 2; kk++) {
            uint32_t Ahi[2][4], Alo[2][4];
            const int arow = rw * 32 + (lane & 15);
            const int akb = kk * 32 + ((lane >> 4) << 4);
            ldsm_x4(Ahi[0], aHi + sw_off(arow, akb));
            ldsm_x4(Ahi[1], aHi + sw_off(arow + 16, akb));
            ldsm_x4(Alo[0], aLo + sw_off(arow, akb));
            ldsm_x4(Alo[1], aLo + sw_off(arow + 16, akb));
            // B via x4: lanes 0-7/8-15 -> n tile (k lo/hi 16B), 16-23/24-31 -> n+1
            const int brow0 = cw * 32 + (lane & 7) + ((lane >> 4) << 3);
            const int bkb = kk * 32 + ((lane & 8) ? 16 : 0);
            #pragma unroll
            for (int np = 0; np < 2; np++) {
                uint32_t bh[4], bl[4];
                ldsm_x4(bh, bHi + sw_off(brow0 + np * 16, bkb));
                ldsm_x4(bl, bLo + sw_off(brow0 + np * 16, bkb));
                #pragma unroll
                for (int h2 = 0; h2 < 2; h2++) {
                    const int n = np * 2 + h2;
                    #pragma unroll
                    for (int mt = 0; mt < 2; mt++) {
                        mma16816(acc[mt][n], Ahi[mt], bh + 2 * h2);
                        mma16816(acc[mt][n], Ahi[mt], bl + 2 * h2);
                        mma16816(acc[mt][n], Alo[mt], bh + 2 * h2);
                    }
                }
            }
        }
    };

    auto zero_acc = [&]() {
        #pragma unroll
        for (int mt = 0; mt < 2; mt++)
            #pragma unroll
            for (int n = 0; n < 4; n++)
                #pragma unroll
                for (int q = 0; q < 4; q++) acc[mt][n][q] = 0.f;
    };

    // ================= phase 1 =================
    zero_acc();
    prefetch1(0, 0); CP_COMMIT();
    prefetch1(1, 1); CP_COMMIT();
    #pragma unroll 1
    for (int c = 0; c < 10; c++) {
        if (c + 1 < 10) CP_WAITG(1);
        else CP_WAITG(0);
        // publishes chunk c AND proves all warps finished mma(c-1) before its
        // ring stage is overwritten by prefetch(c+2)
        __syncthreads();
        if (c + 2 < 10) { prefetch1(c + 2, (c + 2) % 3); CP_COMMIT(); }
        const uint32_t st = usm + RINGO + (c % 3) * 32768;
        chunk_mma(st, st + 8192, st + 16384, st + 24576);
    }
    // epilogue: relu + bias -> split -> sHM
    #pragma unroll
    for (int mt = 0; mt < 2; mt++) {
        const int r0 = rw * 32 + mt * 16 + grp;
        #pragma unroll
        for (int n = 0; n < 4; n++) {
            const int cc = cw * 32 + n * 8 + qid * 2;
            const int ch = cc >> 5;
            const uint32_t kb = (uint32_t)(cc & 31) * 2;
            const float bb0 = sb1[cc], bb1 = sb1[cc + 1];
            unsigned char* base = smem + SHMO + ch * 16384;
            uint32_t o0 = sw_off(r0, kb), o1 = sw_off(r0 + 8, kb);
            sm_store2(base + o0, base + 8192 + o0,
                      fmaxf(acc[mt][n][0] + bb0, 0.f), fmaxf(acc[mt][n][1] + bb1, 0.f));
            sm_store2(base + o1, base + 8192 + o1,
                      fmaxf(acc[mt][n][2] + bb0, 0.f), fmaxf(acc[mt][n][3] + bb1, 0.f));
        }
    }
    __syncthreads();

    // ================= phase 2 =================
    zero_acc();
    prefetch23(2, 0); CP_COMMIT();
    prefetch23(2, 1); CP_COMMIT();
    #pragma unroll 1
    for (int c = 0; c < 2; c++) {
        if (c == 0) CP_WAITG(1);
        else CP_WAITG(0);
        __syncthreads();
        const uint32_t st = usm + RINGO + c * 32768;
        #pragma unroll
        for (int sub = 0; sub < 2; sub++) {
            const int s = c * 2 + sub;
            const uint32_t aB = usm + SHMO + s * 16384;
            const uint32_t bB = st + sub * 16384;
            chunk_mma(aB, aB + 8192, bB, bB + 8192);
        }
    }
    __syncthreads();  // all warps done reading sHM before sM overwrites it
    #pragma unroll
    for (int mt = 0; mt < 2; mt++) {
        const int r0 = rw * 32 + mt * 16 + grp;
        const int rA = srcv[r0], rB = srcv[r0 + 8];
        #pragma unroll
        for (int n = 0; n < 4; n++) {
            const int cc = cw * 32 + n * 8 + qid * 2;
            const int ch = cc >> 5;
            const uint32_t kb = (uint32_t)(cc & 31) * 2;
            const float bb0 = sb2[cc], bb1 = sb2[cc + 1];
            float m00 = acc[mt][n][0] + bb0, m01 = acc[mt][n][1] + bb1;
            float m10 = acc[mt][n][2] + bb0, m11 = acc[mt][n][3] + bb1;
            red_add_v2(&g_maggr[(size_t)rA * 128 + cc], m00, m01);
            red_add_v2(&g_maggr[(size_t)rB * 128 + cc], m10, m11);
            unsigned char* base = smem + SHMO + ch * 16384;
            uint32_t o0 = sw_off(r0, kb), o1 = sw_off(r0 + 8, kb);
            sm_store2(base + o0, base + 8192 + o0, m00, m01);
            sm_store2(base + o1, base + 8192 + o1, m10, m11);
        }
    }
    __syncthreads();

    // ================= phase 3 =================
    zero_acc();
    prefetch23(3, 0); CP_COMMIT();
    prefetch23(3, 1); CP_COMMIT();
    #pragma unroll 1
    for (int c = 0; c < 2; c++) {
        if (c == 0) CP_WAITG(1);
        else CP_WAITG(0);
        __syncthreads();
        const uint32_t st = usm + RINGO + c * 32768;
        #pragma unroll
        for (int sub = 0; sub < 2; sub++) {
            const int s = c * 2 + sub;
            const uint32_t aB = usm + SHMO + s * 16384;
            const uint32_t bB = st + sub * 16384;
            chunk_mma(aB, aB + 8192, bB, bB + 8192);
        }
    }
    __syncthreads();  // all warps done with ring before spm reuses it
    float* spm = (float*)(smem + RINGO);            // [cw][128][16]
    float* spmT = (float*)(smem + RINGO + 32768);   // [128][16]
    #pragma unroll
    for (int mt = 0; mt < 2; mt++) {
        #pragma unroll
        for (int half = 0; half < 2; half++) {
            const int r = rw * 32 + mt * 16 + grp + half * 8;
            float pm[16];
            #pragma unroll
            for (int o = 0; o < 16; o++) pm[o] = 0.f;
            #pragma unroll
            for (int n = 0; n < 4; n++) {
                const int cc = cw * 32 + n * 8 + qid * 2;
                float x0 = fmaxf(acc[mt][n][half * 2 + 0] + sb3[cc], 0.f);
                float x1 = fmaxf(acc[mt][n][half * 2 + 1] + sb3[cc + 1], 0.f);
                const float* w0 = sP2 + cc * 16;
                const float* w1 = w0 + 16;
                #pragma unroll
                for (int o = 0; o < 16; o++) pm[o] += x0 * w0[o] + x1 * w1[o];
            }
            #pragma unroll
            for (int o = 0; o < 16; o++) {
                pm[o] += __shfl_xor_sync(0xffffffffu, pm[o], 1);
                pm[o] += __shfl_xor_sync(0xffffffffu, pm[o], 2);
            }
            #pragma unroll
            for (int j = 0; j < 4; j++)
                spm[cw * 2048 + r * 16 + qid * 4 + j] = pm[qid * 4 + j];
        }
    }
    __syncthreads();
    #pragma unroll
    for (int j = 0; j < 4; j++) {
        const int e = tid + j * 512;
        const int r = e >> 4, o = e & 15;
        spmT[e] = spm[r * 16 + o] + spm[2048 + r * 16 + o]
                + spm[4096 + r * 16 + o] + spm[6144 + r * 16 + o] + spb2[o];
    }
    __syncthreads();
    {
        const int r = tid >> 2;
        const int zb = (tid & 3) * 32;
        const int rc = srcv[r];
        const float* vr = g_vij + (size_t)(e0 + r) * 128;
        #pragma unroll
        for (int z = zb; z < zb + 32; z += 4) {
            float4 vv = *(const float4*)(vr + z);
            float p = spmT[r * 16 + (z >> 3)];
            red_add_v4(&g_paggr[(size_t)rc * 128 + z],
                       vv.x * p, vv.y * p, vv.z * p, vv.w * p);
        }
    }
}

// ---------------- kernel: per-node update ----------------
__global__ __launch_bounds__(128) void node_kernel(
    const float* __restrict__ s, const float* __restrict__ v,
    const float* __restrict__ U1, const float* __restrict__ ub1,
    const float* __restrict__ U2, const float* __restrict__ ub2,
    const float* __restrict__ gl_w, const float* __restrict__ gl_b,
    const float* __restrict__ gr_w, const float* __restrict__ gr_b,
    const float* __restrict__ go_w, const float* __restrict__ go_b,
    const float* __restrict__ ln_a,
    float* __restrict__ out_s, float* __restrict__ out_v)
{
    __shared__ __align__(16) float y[TN][256];
    __shared__ __align__(16) float h[TN][128];
    __shared__ __align__(16) float p[TN][128];
    __shared__ __align__(16) float vo[TN][128];
    __shared__ float cn[TN][16];
    __shared__ float nrm[TN];
    __shared__ float dinv[TN];
    __shared__ float wl[1024], wr[1024], wo[2048];
    __shared__ float wlb[16], wrb[16], wob[16], lna[16];

    const int tid = threadIdx.x;
    const int n0 = blockIdx.x * TN;

    for (int i = tid; i < 1024; i += 128) { wl[i] = gl_w[i]; wr[i] = gr_w[i]; }
    for (int i = tid; i < 2048; i += 128) wo[i] = go_w[i];
    if (tid < 16) { wlb[tid] = gl_b[tid]; wrb[tid] = gr_b[tid];
                    wob[tid] = go_b[tid]; lna[tid] = ln_a[tid]; }
    if (tid < TN) dinv[tid] = rsqrtf(g_deg[n0 + tid]);
    __syncthreads();

    for (int idx = tid; idx < TN * 128; idx += 128) {
        int n = idx >> 7, c = idx & 127;
        y[n][c]       = s[(n0 + n) * 128 + c];
        y[n][128 + c] = g_maggr[(n0 + n) * 128 + c] * dinv[n];
        p[n][c]       = g_paggr[(n0 + n) * 128 + c] * dinv[n];
    }
    __syncthreads();

    {
        float acc[TN];
        float bb = ub1[tid];
        #pragma unroll
        for (int n = 0; n < TN; n++) acc[n] = bb;
        for (int k = 0; k < 256; k += 4) {
            float w0 = U1[(k + 0) * 128 + tid];
            float w1 = U1[(k + 1) * 128 + tid];
            float w2 = U1[(k + 2) * 128 + tid];
            float w3 = U1[(k + 3) * 128 + tid];
            #pragma unroll
            for (int n = 0; n < TN; n++) {
                float4 x = *(const float4*)&y[n][k];
                acc[n] += x.x * w0 + x.y * w1 + x.z * w2 + x.w * w3;
            }
        }
        #pragma unroll
        for (int n = 0; n < TN; n++) h[n][tid] = fmaxf(acc[n], 0.f);
    }
    __syncthreads();

    {
        float acc[TN];
        float bb = ub2[tid];
        #pragma unroll
        for (int n = 0; n < TN; n++) acc[n] = bb;
        for (int k = 0; k < 128; k += 4) {
            float w0 = U2[(k + 0) * 128 + tid];
            float w1 = U2[(k + 1) * 128 + tid];
            float w2 = U2[(k + 2) * 128 + tid];
            float w3 = U2[(k + 3) * 128 + tid];
            #pragma unroll
            for (int n = 0; n < TN; n++) {
                float4 x = *(const float4*)&h[n][k];
                acc[n] += x.x * w0 + x.y * w1 + x.z * w2 + x.w * w3;
            }
        }
        #pragma unroll
        for (int n = 0; n < TN; n++)
            out_s[(n0 + n) * 128 + tid] = y[n][tid] + acc[n];
    }
    __syncthreads();

    for (int idx = tid; idx < TN * 128; idx += 128) {
        int n = idx >> 7, z = idx & 127, o = z >> 3, bl = z & 7;
        int g = c_grade[bl];
        float al = (bl == 0) ? wlb[o] : 0.f;
        float ar = (bl == 0) ? wrb[o] : 0.f;
        #pragma unroll
        for (int c = 0; c < 16; c++) {
            float pv = p[n][c * 8 + bl];
            al += pv * wl[o * 64 + c * 4 + g];
            ar += pv * wr[o * 64 + c * 4 + g];
        }
        y[n][z] = al;
        y[n][128 + z] = ar;
    }
    __syncthreads();

    for (int idx = tid; idx < TN * 16; idx += 128) {
        int n = idx >> 4, c = idx & 15;
        float a[8], b[8], o8[8];
        #pragma unroll
        for (int i = 0; i < 8; i++) {
            a[i] = y[n][c * 8 + i];
            b[i] = y[n][128 + c * 8 + i];
            o8[i] = 0.f;
        }
        #pragma unroll
        for (int i = 0; i < 8; i++)
            #pragma unroll
            for (int j = 0; j < 8; j++)
                o8[RES[i][j]] += SGN[i][j] * a[i] * b[j];
        #pragma unroll
        for (int k = 0; k < 8; k++) h[n][c * 8 + k] = o8[k];
    }
    __syncthreads();

    for (int idx = tid; idx < TN * 128; idx += 128) {
        int n = idx >> 7, z = idx & 127, o = z >> 3, bl = z & 7;
        int g = c_grade[bl];
        float acc = (bl == 0) ? wob[o] : 0.f;
        #pragma unroll
        for (int c = 0; c < 16; c++)
            acc += h[n][c * 8 + bl] * wo[o * 128 + c * 4 + g];
        #pragma unroll
        for (int c = 0; c < 16; c++)
            acc += p[n][c * 8 + bl] * wo[o * 128 + (16 + c) * 4 + g];
        vo[n][z] = acc;
    }
    __syncthreads();

    for (int idx = tid; idx < TN * 16; idx += 128) {
        int n = idx >> 4, c = idx & 15;
        float acc = 0.f;
        #pragma unroll
        for (int bl = 0; bl < 8; bl++) { float x = vo[n][c * 8 + bl]; acc += x * x; }
        cn[n][c] = sqrtf(acc);
    }
    __syncthreads();
    if (tid < TN) {
        float acc = 0.f;
        #pragma unroll
        for (int c = 0; c < 16; c++) acc += cn[tid][c];
        nrm[tid] = acc * (1.f / 16.f) + 1e-6f;
    }
    __syncthreads();
    for (int idx = tid; idx < TN * 128; idx += 128) {
        int n = idx >> 7, z = idx & 127, c = z >> 3;
        out_v[(n0 + n) * 128 + z] = lna[c] * vo[n][z] / nrm[n] + v[(n0 + n) * 128 + z];
    }
}

// ---------------- launcher ----------------
extern "C" void kernel_launch(void* const* d_in, const int* in_sizes, int n_in,
                              void* d_out, int out_size) {
    const float* s     = (const float*)d_in[0];
    const float* v     = (const float*)d_in[1];
    const int*   ei    = (const int*)  d_in[2];
    const float* Wv_w  = (const float*)d_in[3];
    const float* Wv_b  = (const float*)d_in[4];
    const float* mn_W1 = (const float*)d_in[5];
    const float* mn_b1 = (const float*)d_in[6];
    const float* mn_W2 = (const float*)d_in[7];
    const float* mn_b2 = (const float*)d_in[8];
    const float* pn_W1 = (const float*)d_in[9];
    const float* pn_b1 = (const float*)d_in[10];
    const float* pn_W2 = (const float*)d_in[11];
    const float* pn_b2 = (const float*)d_in[12];
    const float* un_W1 = (const float*)d_in[13];
    const float* un_b1 = (const float*)d_in[14];
    const float* un_W2 = (const float*)d_in[15];
    const float* un_b2 = (const float*)d_in[16];
    const float* gl_w  = (const float*)d_in[17];
    const float* gl_b  = (const float*)d_in[18];
    const float* gr_w  = (const float*)d_in[19];
    const float* gr_b  = (const float*)d_in[20];
    const float* go_w  = (const float*)d_in[21];
    const float* go_b  = (const float*)d_in[22];
    const float* ln_a  = (const float*)d_in[23];
    float* out = (float*)d_out;

    cudaFuncSetAttribute(fused_gemm_kernel,
                         cudaFuncAttributeMaxDynamicSharedMemorySize, FUSED_SMEM);

    zero_kernel<<<2048, 256>>>();
    prep_kernel<<<2048, 256>>>(s, mn_W1, mn_W2, pn_W1);
    edge_pre_kernel<<<Ee / TBE, 128>>>(v, ei, Wv_w, Wv_b);
    fused_gemm_kernel<<<Ee / 128, 512, FUSED_SMEM>>>(ei, mn_b1, mn_b2, pn_b1, pn_W2, pn_b2);
    node_kernel<<<Nn / TN, 128>>>(s, v, un_W1, un_b1, un_W2, un_b2,
                                  gl_w, gl_b, gr_w, gr_b, go_w, go_b, ln_a,
                                  out, out + Nn * 128);
}